// round 9
// baseline (speedup 1.0000x reference)
#include <cuda_runtime.h>

#define N_NODES 50000
#define EDGE_F  13
#define HID     32
#define NB      8            // nodes per main block (deg<=32 -> <=256 edges)
#define CH      128          // edges per staging chunk
#define PAIRS   64           // CH/2
#define EFS     66           // EFp/Hp row stride in ull (16B-aligned, even)
#define EX      16           // node-0 slice blocks (first in grid)
#define NBLK    ((N_NODES + NB - 1) / NB)   // 6250
#define SCAN_B  512
#define SCAN_NB ((N_NODES + SCAN_B - 1) / SCAN_B)   // 98

typedef unsigned long long ull;

__device__ ulonglong2 W2Q[128][16];   // k-paired packed W2 (8 KB, L1-hot)
__device__ ull        b2P[8][16];
__device__ ull        Mg0x[EX][256];
__device__ float      Sg0x[EX][16];
__device__ int        StartsG[N_NODES];
__device__ int        PsumG[128];
__device__ int        OffG[128];

// ---- packed fp32x2 helpers (sm_103a FFMA2, PTX-only) ----
__device__ __forceinline__ ull pk2(float a, float b) {
    ull r; asm("mov.b64 %0, {%1,%2};" : "=l"(r) : "f"(a), "f"(b)); return r;
}
__device__ __forceinline__ ull ffma2(ull a, ull b, ull c) {
    ull d; asm("fma.rn.f32x2 %0, %1, %2, %3;" : "=l"(d) : "l"(a), "l"(b), "l"(c)); return d;
}
__device__ __forceinline__ ull add2(ull a, ull b) {
    ull d; asm("add.rn.f32x2 %0, %1, %2;" : "=l"(d) : "l"(a), "l"(b)); return d;
}
__device__ __forceinline__ float2 unpk(ull a) {
    float2 f; asm("mov.b64 {%0,%1}, %2;" : "=f"(f.x), "=f"(f.y) : "l"(a)); return f;
}

// ---------------------------------------------------------------------------
__global__ void pack_kernel(const float* __restrict__ W2, const float* __restrict__ b2)
{
    int tid = threadIdx.x;
    for (int t = tid; t < 128 * 16; t += 256) {
        int k2 = t >> 4, o = t & 15;
        int k0 = 2 * k2, k1 = 2 * k2 + 1;
        int j0 = k0 >> 3, p0 = k0 & 7;
        int j1 = k1 >> 3, p1 = k1 & 7;
        ulonglong2 v;
        v.x = pk2(__ldg(W2 + j0 * 256 + 2 * p0 * 16 + o),
                  __ldg(W2 + j0 * 256 + (2 * p0 + 1) * 16 + o));
        v.y = pk2(__ldg(W2 + j1 * 256 + 2 * p1 * 16 + o),
                  __ldg(W2 + j1 * 256 + (2 * p1 + 1) * 16 + o));
        W2Q[k2][o] = v;
    }
    if (tid < 128) {
        int pp = tid >> 4, o = tid & 15;
        b2P[pp][o] = pk2(__ldg(b2 + 2 * pp * 16 + o),
                         __ldg(b2 + (2 * pp + 1) * 16 + o));
    }
}

__global__ void scan1_kernel(const float* __restrict__ degs)
{
    __shared__ int s[SCAN_B];
    int b = blockIdx.x, t = threadIdx.x, n = b * SCAN_B + t;
    int d = (n < N_NODES) ? (int)degs[n] : 0;
    s[t] = d;
    for (int off = 1; off < SCAN_B; off <<= 1) {
        __syncthreads();
        int v = (t >= off) ? s[t - off] : 0;
        __syncthreads();
        s[t] += v;
    }
    if (n < N_NODES) StartsG[n] = s[t] - d;     // exclusive
    if (t == SCAN_B - 1) PsumG[b] = s[t];
}

__global__ void scan2_kernel()
{
    __shared__ int s[128];
    int t = threadIdx.x;
    s[t] = (t < SCAN_NB) ? PsumG[t] : 0;
    __syncthreads();
    if (t == 0) {
        int acc = 0;
        for (int i = 0; i < SCAN_NB; i++) { int v = s[i]; s[i] = acc; acc += v; }
    }
    __syncthreads();
    if (t < SCAN_NB) OffG[t] = s[t];
}

// ---------------------------------------------------------------------------
struct __align__(16) SmemT {
    ulonglong2 Xq[PAIRS][8];      // 8.0 KB  x pairs, slot = p ^ (q&7)
    ull Mbuf[NB][260];            // 16.6 KB (16B-aligned rows)
    ull Hp[HID][EFS];             // 16.9 KB packed {h(2q), h(2q+1)}; GEMM partials alias
    ull EFp[EDGE_F][EFS];         // 6.9 KB
    ull W1s[EDGE_F][HID];         // 3.3 KB packed {w,w}
    ull b1s[HID];
    ull Sb2[NB][8];
    int sb[NB + 4];
};                                // ~52.5 KB -> 4 blocks/SM

// single masked pair update
#define ACC_ONE(Q, MASK)                                           \
    { ull h2 = hrow[Q] & (MASK);                                   \
      ulonglong2 xv = SM->Xq[Q][p ^ ((Q) & 7)];                    \
      a0 = ffma2(h2, xv.x, a0); a1 = ffma2(h2, xv.y, a1); }
// unmasked pair update
#define ACC_FULL(Q)                                                \
    { ull h2 = hrow[Q];                                            \
      ulonglong2 xv = SM->Xq[Q][p ^ ((Q) & 7)];                    \
      a0 = ffma2(h2, xv.x, a0); a1 = ffma2(h2, xv.y, a1); }
// two pairs (Q even): one LDS.128 on hrow
#define ACC_TWO(Q)                                                 \
    { ulonglong2 h4 = *(const ulonglong2*)&hrow[Q];                \
      ulonglong2 xv0 = SM->Xq[Q][p ^ ((Q) & 7)];                   \
      ulonglong2 xv1 = SM->Xq[(Q) + 1][p ^ (((Q) + 1) & 7)];       \
      a0 = ffma2(h4.x, xv0.x, a0); a1 = ffma2(h4.x, xv0.y, a1);    \
      a0 = ffma2(h4.y, xv1.x, a0); a1 = ffma2(h4.y, xv1.y, a1); }

__global__ void __launch_bounds__(256, 4)
fused_kernel(const float* __restrict__ x,
             const float* __restrict__ ef,
             const float* __restrict__ W1,
             const float* __restrict__ b1,
             const int*   __restrict__ idxn,
             const float* __restrict__ degs,
             float* __restrict__ out,
             int E)
{
    extern __shared__ char smem_raw[];
    SmemT* SM = (SmemT*)smem_raw;
    const int tid = threadIdx.x;
    const int bx  = blockIdx.x;
    const int j = tid >> 3, p = tid & 7;

    for (int t = tid; t < EDGE_F * HID; t += 256) {
        float w = __ldg(W1 + t);
        SM->W1s[t / HID][t % HID] = pk2(w, w);
    }
    if (tid < HID) { float bb = __ldg(b1 + tid); SM->b1s[tid] = pk2(bb, bb); }

    float* EFf = (float*)SM->EFp;       // row stride 2*EFS floats
    const ull* hrow = SM->Hp[j];

    if (bx >= EX) {
        // ================= main blocks: 8 nodes =================
        const int mb = bx - EX;
        const int t0 = (mb == 0) ? 1 : mb * NB;     // node 0 excluded
        int t1 = mb * NB + NB; if (t1 > N_NODES) t1 = N_NODES;
        const int nn = t1 - t0;

        if (tid <= NB) {
            int target = t0 + tid; if (target > t1) target = t1;
            SM->sb[tid] = (target >= N_NODES) ? E
                          : (StartsG[target] + OffG[target >> 9]);
        }
        __syncthreads();

        const int es = SM->sb[0];
        const int ee = SM->sb[NB];
        ull a0 = 0ull, a1 = 0ull, aS = 0ull;

        for (int base = es; base < ee; base += CH) {
            const int c = min(CH, ee - base);
            const int cpad = (c + 1) & ~1;

            // ---- stage ef (zero-padded to cpad) ----
            for (int k = tid; k < cpad * EDGE_F; k += 256) {
                int e = k / EDGE_F, f = k - e * EDGE_F;
                EFf[f * (2 * EFS) + e] =
                    (e < c) ? __ldg(ef + (size_t)base * EDGE_F + k) : 0.f;
            }
            // ---- stage x gather into swizzled ull2 layout ----
            for (int t = tid; t < cpad * 4; t += 256) {
                int e = t >> 2, r = t & 3;
                float4 v = make_float4(0.f, 0.f, 0.f, 0.f);
                if (e < c) {
                    int src = __ldg(idxn + base + e);
                    v = __ldg((const float4*)x + (size_t)src * 4 + r);
                }
                int q = e >> 1, hh = e & 1;
                int s0 = (2 * r) ^ (q & 7), s1 = (2 * r + 1) ^ (q & 7);
                float* c0 = (float*)&SM->Xq[q][s0];
                float* c1 = (float*)&SM->Xq[q][s1];
                c0[hh]     = v.x;
                c0[2 + hh] = v.y;
                c1[hh]     = v.z;
                c1[2 + hh] = v.w;
            }
            __syncthreads();

            // ---- h pairs: paired LDS.128 on EF, STS.128 on Hp ----
            for (int t = tid; t < 512; t += 256) {
                int qb = t >> 5, jj = t & 31;
                ull h0 = SM->b1s[jj], h1 = h0, h2v = h0, h3 = h0;
                #pragma unroll
                for (int f = 0; f < EDGE_F; f++) {
                    ull w = SM->W1s[f][jj];
                    ulonglong2 eA = *(const ulonglong2*)&SM->EFp[f][qb * 4];
                    ulonglong2 eB = *(const ulonglong2*)&SM->EFp[f][qb * 4 + 2];
                    h0  = ffma2(eA.x, w, h0);
                    h1  = ffma2(eA.y, w, h1);
                    h2v = ffma2(eB.x, w, h2v);
                    h3  = ffma2(eB.y, w, h3);
                }
                float2 f0 = unpk(h0), f1 = unpk(h1), f2 = unpk(h2v), f3 = unpk(h3);
                ulonglong2 oA, oB;
                oA.x = pk2(fmaxf(f0.x, 0.f), fmaxf(f0.y, 0.f));
                oA.y = pk2(fmaxf(f1.x, 0.f), fmaxf(f1.y, 0.f));
                oB.x = pk2(fmaxf(f2.x, 0.f), fmaxf(f2.y, 0.f));
                oB.y = pk2(fmaxf(f3.x, 0.f), fmaxf(f3.y, 0.f));
                *(ulonglong2*)&SM->Hp[jj][qb * 4]     = oA;
                *(ulonglong2*)&SM->Hp[jj][qb * 4 + 2] = oB;
            }
            __syncthreads();

            const int cend = base + c;
            #pragma unroll 1
            for (int k = 0; k < NB; k++) {
                const int ak = SM->sb[k], bk = SM->sb[k + 1];
                int aL = ak - base; if (aL < 0) aL = 0;
                int bL = bk - base; if (bL > c) bL = c;
                if (bL > aL) {
                    const int qs = aL >> 1, qe = (bL - 1) >> 1;
                    const ull mlo = (aL & 1) ? 0xFFFFFFFF00000000ull : ~0ull;
                    const ull mhi = (bL & 1) ? 0x00000000FFFFFFFFull : ~0ull;
                    if (qe == qs) {
                        ACC_ONE(qs, mlo & mhi);
                    } else {
                        ACC_ONE(qs, mlo);
                        int q = qs + 1;
                        if ((q & 1) && q < qe) { ACC_FULL(q); q++; }
                        #pragma unroll 2
                        for (; q + 1 < qe; q += 2) ACC_TWO(q);
                        if (q < qe) { ACC_FULL(q); q++; }
                        ACC_ONE(qe, mhi);
                    }
                    if (tid < 16) {   // S accumulation (i = tid)
                        const int ip = tid >> 1, iw = tid & 1;
                        ull x2 = ((const ull*)&SM->Xq[qs][ip ^ (qs & 7)])[iw] & mlo;
                        if (qe == qs) x2 &= mhi;
                        aS = add2(aS, x2);
                        for (int q = qs + 1; q < qe; q++)
                            aS = add2(aS, ((const ull*)&SM->Xq[q][ip ^ (q & 7)])[iw]);
                        if (qe > qs)
                            aS = add2(aS, ((const ull*)&SM->Xq[qe][ip ^ (qe & 7)])[iw] & mhi);
                    }
                }
                if (bk > base && bk <= cend && bk > ak) {   // segment ends here
                    float2 fa = unpk(a0), fb = unpk(a1);
                    SM->Mbuf[k][tid] = pk2(fa.x + fa.y, fb.x + fb.y);
                    a0 = 0ull; a1 = 0ull;
                    if (tid < 16) {
                        float2 fs = unpk(aS);
                        ((float*)SM->Sb2)[k * 16 + tid] = fs.x + fs.y;
                        aS = 0ull;
                    }
                }
            }
            __syncthreads();
        }

        // ---- GEMM: 8-way k-split, each warp covers all 8 nodes ----
        {
            const int w = tid >> 5, lane = tid & 31;
            const int o = lane & 15, gh = lane >> 4;     // gh: node half
            ull s0g = 0ull, s1g = 0ull, s2g = 0ull, s3g = 0ull;
            const int k2b = w * 16;
            #pragma unroll 4
            for (int k2 = k2b; k2 < k2b + 16; k2++) {
                ulonglong2 w2 = __ldg(&W2Q[k2][o]);
                ulonglong2 m0 = *(const ulonglong2*)&SM->Mbuf[gh * 4 + 0][2 * k2];
                ulonglong2 m1 = *(const ulonglong2*)&SM->Mbuf[gh * 4 + 1][2 * k2];
                ulonglong2 m2 = *(const ulonglong2*)&SM->Mbuf[gh * 4 + 2][2 * k2];
                ulonglong2 m3 = *(const ulonglong2*)&SM->Mbuf[gh * 4 + 3][2 * k2];
                s0g = ffma2(m0.x, w2.x, s0g); s0g = ffma2(m0.y, w2.y, s0g);
                s1g = ffma2(m1.x, w2.x, s1g); s1g = ffma2(m1.y, w2.y, s1g);
                s2g = ffma2(m2.x, w2.x, s2g); s2g = ffma2(m2.y, w2.y, s2g);
                s3g = ffma2(m3.x, w2.x, s3g); s3g = ffma2(m3.y, w2.y, s3g);
            }
            ull* Gred = &SM->Hp[0][0];       // Hp dead after last chunk
            Gred[w * 128 + (gh * 4 + 0) * 16 + o] = s0g;
            Gred[w * 128 + (gh * 4 + 1) * 16 + o] = s1g;
            Gred[w * 128 + (gh * 4 + 2) * 16 + o] = s2g;
            Gred[w * 128 + (gh * 4 + 3) * 16 + o] = s3g;
        }
        __syncthreads();
        if (tid < 128) {
            const int g = tid >> 4, o = tid & 15;
            const ull* Gred = &SM->Hp[0][0];
            ull s = Gred[g * 16 + o];
            #pragma unroll
            for (int w = 1; w < 8; w++) s = add2(s, Gred[w * 128 + g * 16 + o]);
            #pragma unroll
            for (int pp = 0; pp < 8; pp++)
                s = ffma2(SM->Sb2[g][pp], __ldg(&b2P[0][0] + pp * 16 + o), s);
            if (g < nn) {
                float2 f = unpk(s);
                float d = __ldg(degs + t0 + g);
                out[(t0 + g) * 16 + o] = (d > 0.f) ? (f.x + f.y) / d : 0.f;
            }
        }
    } else {
        // ================= node-0 slice blocks =================
        const int e0e = (int)__ldg(degs);   // node 0 owns edges [0, degs[0])
        ull a0 = 0ull, a1 = 0ull, aS = 0ull;
        __syncthreads();

        for (int base = bx * CH; base < e0e; base += EX * CH) {
            const int c = min(CH, e0e - base);
            const int cpad = (c + 1) & ~1;
            const int qn = cpad >> 1;

            for (int k = tid; k < cpad * EDGE_F; k += 256) {
                int e = k / EDGE_F, f = k - e * EDGE_F;
                EFf[f * (2 * EFS) + e] =
                    (e < c) ? __ldg(ef + (size_t)base * EDGE_F + k) : 0.f;
            }
            for (int t = tid; t < cpad * 4; t += 256) {
                int e = t >> 2, r = t & 3;
                float4 v = make_float4(0.f, 0.f, 0.f, 0.f);
                if (e < c) {
                    int src = __ldg(idxn + base + e);
                    v = __ldg((const float4*)x + (size_t)src * 4 + r);
                }
                int q = e >> 1, hh = e & 1;
                int s0 = (2 * r) ^ (q & 7), s1 = (2 * r + 1) ^ (q & 7);
                float* c0 = (float*)&SM->Xq[q][s0];
                float* c1 = (float*)&SM->Xq[q][s1];
                c0[hh]     = v.x;
                c0[2 + hh] = v.y;
                c1[hh]     = v.z;
                c1[2 + hh] = v.w;
            }
            __syncthreads();

            for (int t = tid; t < 512; t += 256) {
                int qb = t >> 5, jj = t & 31;
                ull h0 = SM->b1s[jj], h1 = h0, h2v = h0, h3 = h0;
                #pragma unroll
                for (int f = 0; f < EDGE_F; f++) {
                    ull w = SM->W1s[f][jj];
                    ulonglong2 eA = *(const ulonglong2*)&SM->EFp[f][qb * 4];
                    ulonglong2 eB = *(const ulonglong2*)&SM->EFp[f][qb * 4 + 2];
                    h0  = ffma2(eA.x, w, h0);
                    h1  = ffma2(eA.y, w, h1);
                    h2v = ffma2(eB.x, w, h2v);
                    h3  = ffma2(eB.y, w, h3);
                }
                float2 f0 = unpk(h0), f1 = unpk(h1), f2 = unpk(h2v), f3 = unpk(h3);
                ulonglong2 oA, oB;
                oA.x = pk2(fmaxf(f0.x, 0.f), fmaxf(f0.y, 0.f));
                oA.y = pk2(fmaxf(f1.x, 0.f), fmaxf(f1.y, 0.f));
                oB.x = pk2(fmaxf(f2.x, 0.f), fmaxf(f2.y, 0.f));
                oB.y = pk2(fmaxf(f3.x, 0.f), fmaxf(f3.y, 0.f));
                *(ulonglong2*)&SM->Hp[jj][qb * 4]     = oA;
                *(ulonglong2*)&SM->Hp[jj][qb * 4 + 2] = oB;
            }
            __syncthreads();

            {
                int q = 0;
                #pragma unroll 2
                for (; q + 1 < qn; q += 2) ACC_TWO(q);
                if (q < qn) ACC_FULL(q);
            }
            if (tid < 16) {
                const int ip = tid >> 1, iw = tid & 1;
                for (int q = 0; q < qn; q++)
                    aS = add2(aS, ((const ull*)&SM->Xq[q][ip ^ (q & 7)])[iw]);
            }
            __syncthreads();
        }
        float2 fa = unpk(a0), fb = unpk(a1);
        Mg0x[bx][tid] = pk2(fa.x + fa.y, fb.x + fb.y);
        if (tid < 16) {
            float2 fs = unpk(aS);
            Sg0x[bx][tid] = fs.x + fs.y;
        }
    }
}

// ---------------------------------------------------------------------------
__global__ void __launch_bounds__(256)
node0_kernel(const float* __restrict__ degs, float* __restrict__ out)
{
    __shared__ float wred[8][16];
    __shared__ float ssum[16];
    int tid = threadIdx.x, lane = tid & 31, w = tid >> 5;

    ull m = Mg0x[0][tid];
    #pragma unroll
    for (int e2 = 1; e2 < EX; e2++) m = add2(m, Mg0x[e2][tid]);
    if (tid < 16) {
        float s = 0.f;
        #pragma unroll
        for (int e2 = 0; e2 < EX; e2++) s += Sg0x[e2][tid];
        ssum[tid] = s;
    }
    float po[16];
    #pragma unroll
    for (int o = 0; o < 16; o++) {
        ull wk = ((const ull*)&W2Q[tid >> 1][o])[tid & 1];
        ull t2 = ffma2(m, wk, 0ull);
        float2 f = unpk(t2);
        po[o] = f.x + f.y;
    }
    #pragma unroll
    for (int o = 0; o < 16; o++)
        #pragma unroll
        for (int off = 16; off; off >>= 1)
            po[o] += __shfl_down_sync(0xffffffffu, po[o], off);
    if (lane == 0)
        #pragma unroll
        for (int o = 0; o < 16; o++) wred[w][o] = po[o];
    __syncthreads();
    if (tid < 16) {
        float t = 0.f;
        #pragma unroll
        for (int w2 = 0; w2 < 8; w2++) t += wred[w2][tid];
        float s2 = 0.f;
        #pragma unroll
        for (int pp = 0; pp < 8; pp++) {
            ull q = ffma2(pk2(ssum[2 * pp], ssum[2 * pp + 1]), b2P[pp][tid], 0ull);
            float2 f = unpk(q);
            s2 += f.x + f.y;
        }
        float d = __ldg(degs);
        out[tid] = (d > 0.f) ? (t + s2) / d : 0.f;
    }
}

// ---------------------------------------------------------------------------
extern "C" void kernel_launch(void* const* d_in, const int* in_sizes, int n_in,
                              void* d_out, int out_size)
{
    const float* x    = (const float*)d_in[0];
    const float* ef   = (const float*)d_in[1];
    const float* W1   = (const float*)d_in[2];
    const float* b1   = (const float*)d_in[3];
    const float* W2   = (const float*)d_in[4];
    const float* b2   = (const float*)d_in[5];
    const int*   idxn = (const int*)d_in[6];
    const float* degs = (const float*)d_in[8];
    float* out = (float*)d_out;

    const int E = in_sizes[6];
    static int smem_set = 0;
    if (!smem_set) {
        cudaFuncSetAttribute(fused_kernel,
                             cudaFuncAttributeMaxDynamicSharedMemorySize,
                             (int)sizeof(SmemT));
        smem_set = 1;
    }

    pack_kernel<<<1, 256>>>(W2, b2);
    scan1_kernel<<<SCAN_NB, SCAN_B>>>(degs);
    scan2_kernel<<<1, 128>>>();
    fused_kernel<<<EX + NBLK, 256, sizeof(SmemT)>>>(x, ef, W1, b1, idxn, degs, out, E);
    node0_kernel<<<1, 256>>>(degs, out);
}

// round 10
// speedup vs baseline: 1.0037x; 1.0037x over previous
#include <cuda_runtime.h>

#define N_NODES 50000
#define EDGE_F  13
#define HID     32
#define NB      8            // nodes per main block (deg<=32 -> <=256 edges)
#define CH      128          // edges per staging chunk
#define PAIRS   64           // CH/2
#define EFS     66           // EFp/Hp row stride in ull (16B-aligned, even)
#define EX      16           // node-0 slice blocks (first in grid)
#define NBLK    ((N_NODES + NB - 1) / NB)   // 6250
#define SCAN_B  512
#define SCAN_NB ((N_NODES + SCAN_B - 1) / SCAN_B)   // 98

typedef unsigned long long ull;

__device__ ulonglong2 W2Q[128][16];   // k-paired packed W2 (8 KB, L1-hot)
__device__ ull        b2P[8][16];
__device__ ull        Mg0x[EX][256];
__device__ float      Sg0x[EX][16];
__device__ int        StartsG[N_NODES];
__device__ int        PsumG[128];
__device__ int        OffG[128];

// ---- packed fp32x2 helpers (sm_103a FFMA2, PTX-only) ----
__device__ __forceinline__ ull pk2(float a, float b) {
    ull r; asm("mov.b64 %0, {%1,%2};" : "=l"(r) : "f"(a), "f"(b)); return r;
}
__device__ __forceinline__ ull ffma2(ull a, ull b, ull c) {
    ull d; asm("fma.rn.f32x2 %0, %1, %2, %3;" : "=l"(d) : "l"(a), "l"(b), "l"(c)); return d;
}
__device__ __forceinline__ ull add2(ull a, ull b) {
    ull d; asm("add.rn.f32x2 %0, %1, %2;" : "=l"(d) : "l"(a), "l"(b)); return d;
}
__device__ __forceinline__ float2 unpk(ull a) {
    float2 f; asm("mov.b64 {%0,%1}, %2;" : "=f"(f.x), "=f"(f.y) : "l"(a)); return f;
}

// ---------------------------------------------------------------------------
__global__ void pack_kernel(const float* __restrict__ W2, const float* __restrict__ b2)
{
    int tid = threadIdx.x;
    for (int t = tid; t < 128 * 16; t += 256) {
        int k2 = t >> 4, o = t & 15;
        int k0 = 2 * k2, k1 = 2 * k2 + 1;
        int j0 = k0 >> 3, p0 = k0 & 7;
        int j1 = k1 >> 3, p1 = k1 & 7;
        ulonglong2 v;
        v.x = pk2(__ldg(W2 + j0 * 256 + 2 * p0 * 16 + o),
                  __ldg(W2 + j0 * 256 + (2 * p0 + 1) * 16 + o));
        v.y = pk2(__ldg(W2 + j1 * 256 + 2 * p1 * 16 + o),
                  __ldg(W2 + j1 * 256 + (2 * p1 + 1) * 16 + o));
        W2Q[k2][o] = v;
    }
    if (tid < 128) {
        int pp = tid >> 4, o = tid & 15;
        b2P[pp][o] = pk2(__ldg(b2 + 2 * pp * 16 + o),
                         __ldg(b2 + (2 * pp + 1) * 16 + o));
    }
}

__global__ void scan1_kernel(const float* __restrict__ degs)
{
    __shared__ int s[SCAN_B];
    int b = blockIdx.x, t = threadIdx.x, n = b * SCAN_B + t;
    int d = (n < N_NODES) ? (int)degs[n] : 0;
    s[t] = d;
    for (int off = 1; off < SCAN_B; off <<= 1) {
        __syncthreads();
        int v = (t >= off) ? s[t - off] : 0;
        __syncthreads();
        s[t] += v;
    }
    if (n < N_NODES) StartsG[n] = s[t] - d;     // exclusive
    if (t == SCAN_B - 1) PsumG[b] = s[t];
}

__global__ void scan2_kernel()
{
    __shared__ int s[128];
    int t = threadIdx.x;
    s[t] = (t < SCAN_NB) ? PsumG[t] : 0;
    __syncthreads();
    if (t == 0) {
        int acc = 0;
        for (int i = 0; i < SCAN_NB; i++) { int v = s[i]; s[i] = acc; acc += v; }
    }
    __syncthreads();
    if (t < SCAN_NB) OffG[t] = s[t];
}

// ---------------------------------------------------------------------------
struct __align__(16) SmemT {
    ulonglong2 Xq[PAIRS][8];      // 8.0 KB  x pairs, PLAIN [q][p] (reads conflict-free)
    ull Mbuf[NB][260];            // 16.6 KB (16B-aligned rows)
    ull Hp[HID][EFS];             // 16.9 KB packed {h(2q), h(2q+1)}; GEMM partials alias
    ull EFp[EDGE_F][EFS];         // 6.9 KB
    ull W1s[EDGE_F][HID];         // 3.3 KB packed {w,w}
    ull b1s[HID];
    ull Sb2[NB][8];
    int sb[NB + 4];
};                                // ~52.5 KB -> 4 blocks/SM

__global__ void __launch_bounds__(256, 4)
fused_kernel(const float* __restrict__ x,
             const float* __restrict__ ef,
             const float* __restrict__ W1,
             const float* __restrict__ b1,
             const int*   __restrict__ idxn,
             const float* __restrict__ degs,
             float* __restrict__ out,
             int E)
{
    extern __shared__ char smem_raw[];
    SmemT* SM = (SmemT*)smem_raw;
    const int tid = threadIdx.x;
    const int bx  = blockIdx.x;
    const int j = tid >> 3, p = tid & 7;

    for (int t = tid; t < EDGE_F * HID; t += 256) {
        float w = __ldg(W1 + t);
        SM->W1s[t / HID][t % HID] = pk2(w, w);
    }
    if (tid < HID) { float bb = __ldg(b1 + tid); SM->b1s[tid] = pk2(bb, bb); }

    float* EFf = (float*)SM->EFp;       // row stride 2*EFS floats
    const ull* hrow = SM->Hp[j];
    const ulonglong2* xrow = &SM->Xq[0][p];    // advance by 8 per q

    if (bx >= EX) {
        // ================= main blocks: 8 nodes =================
        const int mb = bx - EX;
        const int t0 = (mb == 0) ? 1 : mb * NB;     // node 0 excluded
        int t1 = mb * NB + NB; if (t1 > N_NODES) t1 = N_NODES;
        const int nn = t1 - t0;

        if (tid <= NB) {
            int target = t0 + tid; if (target > t1) target = t1;
            SM->sb[tid] = (target >= N_NODES) ? E
                          : (StartsG[target] + OffG[target >> 9]);
        }
        __syncthreads();

        const int es = SM->sb[0];
        const int ee = SM->sb[NB];
        ull a0 = 0ull, a1 = 0ull, aS = 0ull;

        for (int base = es; base < ee; base += CH) {
            const int c = min(CH, ee - base);
            const int cpad = (c + 1) & ~1;

            // ---- stage ef (zero-padded to cpad) ----
            for (int k = tid; k < cpad * EDGE_F; k += 256) {
                int e = k / EDGE_F, f = k - e * EDGE_F;
                EFf[f * (2 * EFS) + e] =
                    (e < c) ? __ldg(ef + (size_t)base * EDGE_F + k) : 0.f;
            }
            // ---- stage x gather, plain layout (minor write conflicts OK) ----
            for (int t = tid; t < cpad * 4; t += 256) {
                int e = t >> 2, r = t & 3;
                float4 v = make_float4(0.f, 0.f, 0.f, 0.f);
                if (e < c) {
                    int src = __ldg(idxn + base + e);
                    v = __ldg((const float4*)x + (size_t)src * 4 + r);
                }
                int q = e >> 1, hh = e & 1;
                float* c0 = (float*)&SM->Xq[q][2 * r];
                float* c1 = (float*)&SM->Xq[q][2 * r + 1];
                c0[hh]     = v.x;   // i=4r   (.x half of slot 2r)
                c0[2 + hh] = v.y;   // i=4r+1 (.y half of slot 2r)
                c1[hh]     = v.z;   // i=4r+2
                c1[2 + hh] = v.w;   // i=4r+3
            }
            __syncthreads();

            // ---- h pairs: paired LDS.128 on EF, STS.128 on Hp ----
            for (int t = tid; t < 512; t += 256) {
                int qb = t >> 5, jj = t & 31;
                ull h0 = SM->b1s[jj], h1 = h0, h2v = h0, h3 = h0;
                #pragma unroll
                for (int f = 0; f < EDGE_F; f++) {
                    ull w = SM->W1s[f][jj];
                    ulonglong2 eA = *(const ulonglong2*)&SM->EFp[f][qb * 4];
                    ulonglong2 eB = *(const ulonglong2*)&SM->EFp[f][qb * 4 + 2];
                    h0  = ffma2(eA.x, w, h0);
                    h1  = ffma2(eA.y, w, h1);
                    h2v = ffma2(eB.x, w, h2v);
                    h3  = ffma2(eB.y, w, h3);
                }
                float2 f0 = unpk(h0), f1 = unpk(h1), f2 = unpk(h2v), f3 = unpk(h3);
                ulonglong2 oA, oB;
                oA.x = pk2(fmaxf(f0.x, 0.f), fmaxf(f0.y, 0.f));
                oA.y = pk2(fmaxf(f1.x, 0.f), fmaxf(f1.y, 0.f));
                oB.x = pk2(fmaxf(f2.x, 0.f), fmaxf(f2.y, 0.f));
                oB.y = pk2(fmaxf(f3.x, 0.f), fmaxf(f3.y, 0.f));
                *(ulonglong2*)&SM->Hp[jj][qb * 4]     = oA;
                *(ulonglong2*)&SM->Hp[jj][qb * 4 + 2] = oB;
            }
            __syncthreads();

            const int cend = base + c;
            #pragma unroll 1
            for (int k = 0; k < NB; k++) {
                const int ak = SM->sb[k], bk = SM->sb[k + 1];
                int aL = ak - base; if (aL < 0) aL = 0;
                int bL = bk - base; if (bL > c) bL = c;
                if (bL > aL) {
                    const int qs = aL >> 1, qe = (bL - 1) >> 1;
                    const ull mlo = (aL & 1) ? 0xFFFFFFFF00000000ull : ~0ull;
                    const ull mhi = (bL & 1) ? 0x00000000FFFFFFFFull : ~0ull;
                    const ull* hp = &hrow[qs];
                    const ulonglong2* xp = xrow + (size_t)qs * 8;
                    if (qe == qs) {
                        ull h2 = *hp & (mlo & mhi);
                        ulonglong2 xv = *xp;
                        a0 = ffma2(h2, xv.x, a0); a1 = ffma2(h2, xv.y, a1);
                    } else {
                        {   // first (masked)
                            ull h2 = *hp & mlo;
                            ulonglong2 xv = *xp;
                            a0 = ffma2(h2, xv.x, a0); a1 = ffma2(h2, xv.y, a1);
                            hp++; xp += 8;
                        }
                        int q = qs + 1;
                        if ((q & 1) && q < qe) {       // align to even q
                            ull h2 = *hp;
                            ulonglong2 xv = *xp;
                            a0 = ffma2(h2, xv.x, a0); a1 = ffma2(h2, xv.y, a1);
                            hp++; xp += 8; q++;
                        }
                        #pragma unroll 2
                        for (; q + 1 < qe; q += 2) {   // two pairs: LDS.128 on h
                            ulonglong2 h4 = *(const ulonglong2*)hp;
                            ulonglong2 xv0 = xp[0];
                            ulonglong2 xv1 = xp[8];
                            a0 = ffma2(h4.x, xv0.x, a0); a1 = ffma2(h4.x, xv0.y, a1);
                            a0 = ffma2(h4.y, xv1.x, a0); a1 = ffma2(h4.y, xv1.y, a1);
                            hp += 2; xp += 16;
                        }
                        if (q < qe) {
                            ull h2 = *hp;
                            ulonglong2 xv = *xp;
                            a0 = ffma2(h2, xv.x, a0); a1 = ffma2(h2, xv.y, a1);
                            hp++; xp += 8; q++;
                        }
                        {   // last (masked)
                            ull h2 = *hp & mhi;
                            ulonglong2 xv = *xp;
                            a0 = ffma2(h2, xv.x, a0); a1 = ffma2(h2, xv.y, a1);
                        }
                    }
                    if (tid < 16) {   // S accumulation (i = tid)
                        const int ip = tid >> 1, iw = tid & 1;
                        const ull* xrp = (const ull*)&SM->Xq[qs][ip] + iw;
                        ull x2 = *xrp & mlo;
                        if (qe == qs) x2 &= mhi;
                        aS = add2(aS, x2);
                        xrp += 16;
                        for (int q = qs + 1; q < qe; q++, xrp += 16)
                            aS = add2(aS, *xrp);
                        if (qe > qs) aS = add2(aS, *xrp & mhi);
                    }
                }
                if (bk > base && bk <= cend && bk > ak) {   // segment ends here
                    float2 fa = unpk(a0), fb = unpk(a1);
                    SM->Mbuf[k][tid] = pk2(fa.x + fa.y, fb.x + fb.y);
                    a0 = 0ull; a1 = 0ull;
                    if (tid < 16) {
                        float2 fs = unpk(aS);
                        ((float*)SM->Sb2)[k * 16 + tid] = fs.x + fs.y;
                        aS = 0ull;
                    }
                }
            }
            __syncthreads();
        }

        // ---- GEMM: 8-way k-split, each warp covers all 8 nodes ----
        {
            const int w = tid >> 5, lane = tid & 31;
            const int o = lane & 15, gh = lane >> 4;     // gh: node half
            ull s0g = 0ull, s1g = 0ull, s2g = 0ull, s3g = 0ull;
            const ulonglong2* wp = &W2Q[w * 16][o];
            const ull* mb0 = &SM->Mbuf[gh * 4 + 0][2 * (w * 16)];
            const ull* mb1 = &SM->Mbuf[gh * 4 + 1][2 * (w * 16)];
            const ull* mb2 = &SM->Mbuf[gh * 4 + 2][2 * (w * 16)];
            const ull* mb3 = &SM->Mbuf[gh * 4 + 3][2 * (w * 16)];
            #pragma unroll 4
            for (int it = 0; it < 16; it++) {
                ulonglong2 w2 = __ldg(wp); wp += 16;
                ulonglong2 m0 = *(const ulonglong2*)mb0; mb0 += 2;
                ulonglong2 m1 = *(const ulonglong2*)mb1; mb1 += 2;
                ulonglong2 m2 = *(const ulonglong2*)mb2; mb2 += 2;
                ulonglong2 m3 = *(const ulonglong2*)mb3; mb3 += 2;
                s0g = ffma2(m0.x, w2.x, s0g); s0g = ffma2(m0.y, w2.y, s0g);
                s1g = ffma2(m1.x, w2.x, s1g); s1g = ffma2(m1.y, w2.y, s1g);
                s2g = ffma2(m2.x, w2.x, s2g); s2g = ffma2(m2.y, w2.y, s2g);
                s3g = ffma2(m3.x, w2.x, s3g); s3g = ffma2(m3.y, w2.y, s3g);
            }
            ull* Gred = &SM->Hp[0][0];       // Hp dead after last chunk
            Gred[w * 128 + (gh * 4 + 0) * 16 + o] = s0g;
            Gred[w * 128 + (gh * 4 + 1) * 16 + o] = s1g;
            Gred[w * 128 + (gh * 4 + 2) * 16 + o] = s2g;
            Gred[w * 128 + (gh * 4 + 3) * 16 + o] = s3g;
        }
        __syncthreads();
        if (tid < 128) {
            const int g = tid >> 4, o = tid & 15;
            const ull* Gred = &SM->Hp[0][0];
            ull s = Gred[g * 16 + o];
            #pragma unroll
            for (int w = 1; w < 8; w++) s = add2(s, Gred[w * 128 + g * 16 + o]);
            #pragma unroll
            for (int pp = 0; pp < 8; pp++)
                s = ffma2(SM->Sb2[g][pp], __ldg(&b2P[0][0] + pp * 16 + o), s);
            if (g < nn) {
                float2 f = unpk(s);
                float d = __ldg(degs + t0 + g);
                out[(t0 + g) * 16 + o] = (d > 0.f) ? (f.x + f.y) / d : 0.f;
            }
        }
    } else {
        // ================= node-0 slice blocks =================
        const int e0e = (int)__ldg(degs);   // node 0 owns edges [0, degs[0])
        ull a0 = 0ull, a1 = 0ull, aS = 0ull;
        __syncthreads();

        for (int base = bx * CH; base < e0e; base += EX * CH) {
            const int c = min(CH, e0e - base);
            const int cpad = (c + 1) & ~1;
            const int qn = cpad >> 1;

            for (int k = tid; k < cpad * EDGE_F; k += 256) {
                int e = k / EDGE_F, f = k - e * EDGE_F;
                EFf[f * (2 * EFS) + e] =
                    (e < c) ? __ldg(ef + (size_t)base * EDGE_F + k) : 0.f;
            }
            for (int t = tid; t < cpad * 4; t += 256) {
                int e = t >> 2, r = t & 3;
                float4 v = make_float4(0.f, 0.f, 0.f, 0.f);
                if (e < c) {
                    int src = __ldg(idxn + base + e);
                    v = __ldg((const float4*)x + (size_t)src * 4 + r);
                }
                int q = e >> 1, hh = e & 1;
                float* c0 = (float*)&SM->Xq[q][2 * r];
                float* c1 = (float*)&SM->Xq[q][2 * r + 1];
                c0[hh]     = v.x;
                c0[2 + hh] = v.y;
                c1[hh]     = v.z;
                c1[2 + hh] = v.w;
            }
            __syncthreads();

            for (int t = tid; t < 512; t += 256) {
                int qb = t >> 5, jj = t & 31;
                ull h0 = SM->b1s[jj], h1 = h0, h2v = h0, h3 = h0;
                #pragma unroll
                for (int f = 0; f < EDGE_F; f++) {
                    ull w = SM->W1s[f][jj];
                    ulonglong2 eA = *(const ulonglong2*)&SM->EFp[f][qb * 4];
                    ulonglong2 eB = *(const ulonglong2*)&SM->EFp[f][qb * 4 + 2];
                    h0  = ffma2(eA.x, w, h0);
                    h1  = ffma2(eA.y, w, h1);
                    h2v = ffma2(eB.x, w, h2v);
                    h3  = ffma2(eB.y, w, h3);
                }
                float2 f0 = unpk(h0), f1 = unpk(h1), f2 = unpk(h2v), f3 = unpk(h3);
                ulonglong2 oA, oB;
                oA.x = pk2(fmaxf(f0.x, 0.f), fmaxf(f0.y, 0.f));
                oA.y = pk2(fmaxf(f1.x, 0.f), fmaxf(f1.y, 0.f));
                oB.x = pk2(fmaxf(f2.x, 0.f), fmaxf(f2.y, 0.f));
                oB.y = pk2(fmaxf(f3.x, 0.f), fmaxf(f3.y, 0.f));
                *(ulonglong2*)&SM->Hp[jj][qb * 4]     = oA;
                *(ulonglong2*)&SM->Hp[jj][qb * 4 + 2] = oB;
            }
            __syncthreads();

            {
                const ull* hp = hrow;
                const ulonglong2* xp = xrow;
                int q = 0;
                #pragma unroll 2
                for (; q + 1 < qn; q += 2) {
                    ulonglong2 h4 = *(const ulonglong2*)hp;
                    ulonglong2 xv0 = xp[0];
                    ulonglong2 xv1 = xp[8];
                    a0 = ffma2(h4.x, xv0.x, a0); a1 = ffma2(h4.x, xv0.y, a1);
                    a0 = ffma2(h4.y, xv1.x, a0); a1 = ffma2(h4.y, xv1.y, a1);
                    hp += 2; xp += 16;
                }
                if (q < qn) {
                    ull h2 = *hp;
                    ulonglong2 xv = *xp;
                    a0 = ffma2(h2, xv.x, a0); a1 = ffma2(h2, xv.y, a1);
                }
            }
            if (tid < 16) {
                const int ip = tid >> 1, iw = tid & 1;
                const ull* xrp = (const ull*)&SM->Xq[0][ip] + iw;
                for (int q = 0; q < qn; q++, xrp += 16)
                    aS = add2(aS, *xrp);
            }
            __syncthreads();
        }
        float2 fa = unpk(a0), fb = unpk(a1);
        Mg0x[bx][tid] = pk2(fa.x + fa.y, fb.x + fb.y);
        if (tid < 16) {
            float2 fs = unpk(aS);
            Sg0x[bx][tid] = fs.x + fs.y;
        }
    }
}

// ---------------------------------------------------------------------------
__global__ void __launch_bounds__(256)
node0_kernel(const float* __restrict__ degs, float* __restrict__ out)
{
    __shared__ float wred[8][16];
    __shared__ float ssum[16];
    int tid = threadIdx.x, lane = tid & 31, w = tid >> 5;

    ull m = Mg0x[0][tid];
    #pragma unroll
    for (int e2 = 1; e2 < EX; e2++) m = add2(m, Mg0x[e2][tid]);
    if (tid < 16) {
        float s = 0.f;
        #pragma unroll
        for (int e2 = 0; e2 < EX; e2++) s += Sg0x[e2][tid];
        ssum[tid] = s;
    }
    float po[16];
    #pragma unroll
    for (int o = 0; o < 16; o++) {
        ull wk = ((const ull*)&W2Q[tid >> 1][o])[tid & 1];
        ull t2 = ffma2(m, wk, 0ull);
        float2 f = unpk(t2);
        po[o] = f.x + f.y;
    }
    #pragma unroll
    for (int o = 0; o < 16; o++)
        #pragma unroll
        for (int off = 16; off; off >>= 1)
            po[o] += __shfl_down_sync(0xffffffffu, po[o], off);
    if (lane == 0)
        #pragma unroll
        for (int o = 0; o < 16; o++) wred[w][o] = po[o];
    __syncthreads();
    if (tid < 16) {
        float t = 0.f;
        #pragma unroll
        for (int w2 = 0; w2 < 8; w2++) t += wred[w2][tid];
        float s2 = 0.f;
        #pragma unroll
        for (int pp = 0; pp < 8; pp++) {
            ull q = ffma2(pk2(ssum[2 * pp], ssum[2 * pp + 1]), b2P[pp][tid], 0ull);
            float2 f = unpk(q);
            s2 += f.x + f.y;
        }
        float d = __ldg(degs);
        out[tid] = (d > 0.f) ? (t + s2) / d : 0.f;
    }
}

// ---------------------------------------------------------------------------
extern "C" void kernel_launch(void* const* d_in, const int* in_sizes, int n_in,
                              void* d_out, int out_size)
{
    const float* x    = (const float*)d_in[0];
    const float* ef   = (const float*)d_in[1];
    const float* W1   = (const float*)d_in[2];
    const float* b1   = (const float*)d_in[3];
    const float* W2   = (const float*)d_in[4];
    const float* b2   = (const float*)d_in[5];
    const int*   idxn = (const int*)d_in[6];
    const float* degs = (const float*)d_in[8];
    float* out = (float*)d_out;

    const int E = in_sizes[6];
    static int smem_set = 0;
    if (!smem_set) {
        cudaFuncSetAttribute(fused_kernel,
                             cudaFuncAttributeMaxDynamicSharedMemorySize,
                             (int)sizeof(SmemT));
        smem_set = 1;
    }

    pack_kernel<<<1, 256>>>(W2, b2);
    scan1_kernel<<<SCAN_NB, SCAN_B>>>(degs);
    scan2_kernel<<<1, 128>>>();
    fused_kernel<<<EX + NBLK, 256, sizeof(SmemT)>>>(x, ef, W1, b1, idxn, degs, out, E);
    node0_kernel<<<1, 256>>>(degs, out);
}

// round 11
// speedup vs baseline: 1.0230x; 1.0193x over previous
#include <cuda_runtime.h>

#define N_NODES 50000
#define EDGE_F  13
#define HID     32
#define NB      8            // nodes per main block (deg<=32 -> <=256 edges)
#define CH      128          // edges per staging chunk
#define PAIRS   64           // CH/2
#define EFS     66           // EFp/Hp row stride in ull (16B-aligned, even)
#define EX      16           // node-0 slice blocks (first in grid)
#define NBLK    ((N_NODES + NB - 1) / NB)   // 6250
#define SCAN_B  512
#define SCAN_NB ((N_NODES + SCAN_B - 1) / SCAN_B)   // 98

typedef unsigned long long ull;

__device__ ulonglong2 W2Q[128][16];   // k-paired packed W2 (8 KB, L1-hot)
__device__ ull        b2P[8][16];
__device__ ull        Mg0x[EX][256];
__device__ float      Sg0x[EX][16];
__device__ int        StartsG[N_NODES];
__device__ int        PsumG[128];
__device__ int        OffG[128];

// ---- packed fp32x2 helpers (sm_103a FFMA2, PTX-only) ----
__device__ __forceinline__ ull pk2(float a, float b) {
    ull r; asm("mov.b64 %0, {%1,%2};" : "=l"(r) : "f"(a), "f"(b)); return r;
}
__device__ __forceinline__ ull ffma2(ull a, ull b, ull c) {
    ull d; asm("fma.rn.f32x2 %0, %1, %2, %3;" : "=l"(d) : "l"(a), "l"(b), "l"(c)); return d;
}
__device__ __forceinline__ ull add2(ull a, ull b) {
    ull d; asm("add.rn.f32x2 %0, %1, %2;" : "=l"(d) : "l"(a), "l"(b)); return d;
}
__device__ __forceinline__ float2 unpk(ull a) {
    float2 f; asm("mov.b64 {%0,%1}, %2;" : "=f"(f.x), "=f"(f.y) : "l"(a)); return f;
}

// ---------------------------------------------------------------------------
// scan1 + pack fused: blocks [0, SCAN_NB) scan degs; block SCAN_NB packs W2/b2
// ---------------------------------------------------------------------------
__global__ void scan1_kernel(const float* __restrict__ degs,
                             const float* __restrict__ W2,
                             const float* __restrict__ b2)
{
    if (blockIdx.x == SCAN_NB) {
        int tid = threadIdx.x;
        for (int t = tid; t < 128 * 16; t += SCAN_B) {
            int k2 = t >> 4, o = t & 15;
            int k0 = 2 * k2, k1 = 2 * k2 + 1;
            int j0 = k0 >> 3, p0 = k0 & 7;
            int j1 = k1 >> 3, p1 = k1 & 7;
            ulonglong2 v;
            v.x = pk2(__ldg(W2 + j0 * 256 + 2 * p0 * 16 + o),
                      __ldg(W2 + j0 * 256 + (2 * p0 + 1) * 16 + o));
            v.y = pk2(__ldg(W2 + j1 * 256 + 2 * p1 * 16 + o),
                      __ldg(W2 + j1 * 256 + (2 * p1 + 1) * 16 + o));
            W2Q[k2][o] = v;
        }
        if (tid < 128) {
            int pp = tid >> 4, o = tid & 15;
            b2P[pp][o] = pk2(__ldg(b2 + 2 * pp * 16 + o),
                             __ldg(b2 + (2 * pp + 1) * 16 + o));
        }
        return;
    }
    __shared__ int s[SCAN_B];
    int b = blockIdx.x, t = threadIdx.x, n = b * SCAN_B + t;
    int d = (n < N_NODES) ? (int)degs[n] : 0;
    s[t] = d;
    for (int off = 1; off < SCAN_B; off <<= 1) {
        __syncthreads();
        int v = (t >= off) ? s[t - off] : 0;
        __syncthreads();
        s[t] += v;
    }
    if (n < N_NODES) StartsG[n] = s[t] - d;     // exclusive
    if (t == SCAN_B - 1) PsumG[b] = s[t];
}

__global__ void scan2_kernel()
{
    __shared__ int s[128];
    int t = threadIdx.x;
    s[t] = (t < SCAN_NB) ? PsumG[t] : 0;
    __syncthreads();
    if (t == 0) {
        int acc = 0;
        for (int i = 0; i < SCAN_NB; i++) { int v = s[i]; s[i] = acc; acc += v; }
    }
    __syncthreads();
    if (t < SCAN_NB) OffG[t] = s[t];
}

// ---------------------------------------------------------------------------
struct __align__(16) SmemT {
    ulonglong2 Xq[PAIRS][8];      // 8.0 KB  x pairs, plain [q][p]
    ull Mbuf[NB][260];            // 16.6 KB (16B-aligned rows)
    ull Hp[HID][EFS];             // 16.9 KB packed {h(2q), h(2q+1)}; GEMM partials alias
    ull EFp[EDGE_F][EFS];         // 6.9 KB
    ull W1s[EDGE_F][HID];         // 3.3 KB packed {w,w}
    ull b1s[HID];
    ull Sb2[NB][8];
    int sb[NB + 4];
};                                // ~52.5 KB -> 4 blocks/SM

// h-compute: one 8-pair group per thread (qb = tid>>5, jj = tid&31).
// Per f: 4 warp-uniform LDS.128 on EF + 1 W1 LDS.64 -> W1 traffic halved.
#define H_COMPUTE()                                                        \
    {                                                                      \
        const int qb = tid >> 5, jj = tid & 31;                            \
        ull hh0, hh1, hh2, hh3, hh4, hh5, hh6, hh7;                        \
        { ull bb = SM->b1s[jj];                                            \
          hh0 = bb; hh1 = bb; hh2 = bb; hh3 = bb;                          \
          hh4 = bb; hh5 = bb; hh6 = bb; hh7 = bb; }                        \
        _Pragma("unroll")                                                  \
        for (int f = 0; f < EDGE_F; f++) {                                 \
            ull w = SM->W1s[f][jj];                                        \
            const ull* efr = &SM->EFp[f][qb * 8];                          \
            ulonglong2 eA = *(const ulonglong2*)(efr);                     \
            ulonglong2 eB = *(const ulonglong2*)(efr + 2);                 \
            hh0 = ffma2(eA.x, w, hh0); hh1 = ffma2(eA.y, w, hh1);          \
            hh2 = ffma2(eB.x, w, hh2); hh3 = ffma2(eB.y, w, hh3);          \
            ulonglong2 eC = *(const ulonglong2*)(efr + 4);                 \
            ulonglong2 eD = *(const ulonglong2*)(efr + 6);                 \
            hh4 = ffma2(eC.x, w, hh4); hh5 = ffma2(eC.y, w, hh5);          \
            hh6 = ffma2(eD.x, w, hh6); hh7 = ffma2(eD.y, w, hh7);          \
        }                                                                  \
        ull* hdst = &SM->Hp[jj][qb * 8];                                   \
        float2 fA, fB; ulonglong2 ov;                                      \
        fA = unpk(hh0); fB = unpk(hh1);                                    \
        ov.x = pk2(fmaxf(fA.x, 0.f), fmaxf(fA.y, 0.f));                    \
        ov.y = pk2(fmaxf(fB.x, 0.f), fmaxf(fB.y, 0.f));                    \
        *(ulonglong2*)(hdst) = ov;                                         \
        fA = unpk(hh2); fB = unpk(hh3);                                    \
        ov.x = pk2(fmaxf(fA.x, 0.f), fmaxf(fA.y, 0.f));                    \
        ov.y = pk2(fmaxf(fB.x, 0.f), fmaxf(fB.y, 0.f));                    \
        *(ulonglong2*)(hdst + 2) = ov;                                     \
        fA = unpk(hh4); fB = unpk(hh5);                                    \
        ov.x = pk2(fmaxf(fA.x, 0.f), fmaxf(fA.y, 0.f));                    \
        ov.y = pk2(fmaxf(fB.x, 0.f), fmaxf(fB.y, 0.f));                    \
        *(ulonglong2*)(hdst + 4) = ov;                                     \
        fA = unpk(hh6); fB = unpk(hh7);                                    \
        ov.x = pk2(fmaxf(fA.x, 0.f), fmaxf(fA.y, 0.f));                    \
        ov.y = pk2(fmaxf(fB.x, 0.f), fmaxf(fB.y, 0.f));                    \
        *(ulonglong2*)(hdst + 6) = ov;                                     \
    }

__global__ void __launch_bounds__(256, 4)
fused_kernel(const float* __restrict__ x,
             const float* __restrict__ ef,
             const float* __restrict__ W1,
             const float* __restrict__ b1,
             const int*   __restrict__ idxn,
             const float* __restrict__ degs,
             float* __restrict__ out,
             int E)
{
    extern __shared__ char smem_raw[];
    SmemT* SM = (SmemT*)smem_raw;
    const int tid = threadIdx.x;
    const int bx  = blockIdx.x;
    const int j = tid >> 3, p = tid & 7;

    for (int t = tid; t < EDGE_F * HID; t += 256) {
        float w = __ldg(W1 + t);
        SM->W1s[t / HID][t % HID] = pk2(w, w);
    }
    if (tid < HID) { float bb = __ldg(b1 + tid); SM->b1s[tid] = pk2(bb, bb); }

    float* EFf = (float*)SM->EFp;       // row stride 2*EFS floats
    const ull* hrow = SM->Hp[j];
    const ulonglong2* xrow = &SM->Xq[0][p];    // advance by 8 per q

    if (bx >= EX) {
        // ================= main blocks: 8 nodes =================
        const int mb = bx - EX;
        const int t0 = (mb == 0) ? 1 : mb * NB;     // node 0 excluded
        int t1 = mb * NB + NB; if (t1 > N_NODES) t1 = N_NODES;
        const int nn = t1 - t0;

        if (tid <= NB) {
            int target = t0 + tid; if (target > t1) target = t1;
            SM->sb[tid] = (target >= N_NODES) ? E
                          : (StartsG[target] + OffG[target >> 9]);
        }
        __syncthreads();

        const int es = SM->sb[0];
        const int ee = SM->sb[NB];
        ull a0 = 0ull, a1 = 0ull, aS = 0ull;

        for (int base = es; base < ee; base += CH) {
            const int c = min(CH, ee - base);
            const int cpad = (c + 1) & ~1;

            // ---- stage ef (zero-padded to cpad) ----
            for (int k = tid; k < cpad * EDGE_F; k += 256) {
                int e = k / EDGE_F, f = k - e * EDGE_F;
                EFf[f * (2 * EFS) + e] =
                    (e < c) ? __ldg(ef + (size_t)base * EDGE_F + k) : 0.f;
            }
            // ---- stage x gather ----
            for (int t = tid; t < cpad * 4; t += 256) {
                int e = t >> 2, r = t & 3;
                float4 v = make_float4(0.f, 0.f, 0.f, 0.f);
                if (e < c) {
                    int src = __ldg(idxn + base + e);
                    v = __ldg((const float4*)x + (size_t)src * 4 + r);
                }
                int q = e >> 1, hh = e & 1;
                float* c0 = (float*)&SM->Xq[q][2 * r];
                float* c1 = (float*)&SM->Xq[q][2 * r + 1];
                c0[hh]     = v.x;
                c0[2 + hh] = v.y;
                c1[hh]     = v.z;
                c1[2 + hh] = v.w;
            }
            __syncthreads();

            // ---- h: 8-pair group per thread ----
            H_COMPUTE();
            __syncthreads();

            const int cend = base + c;
            #pragma unroll 1
            for (int k = 0; k < NB; k++) {
                const int ak = SM->sb[k], bk = SM->sb[k + 1];
                int aL = ak - base; if (aL < 0) aL = 0;
                int bL = bk - base; if (bL > c) bL = c;
                if (bL > aL) {
                    const int qs = aL >> 1, qe = (bL - 1) >> 1;
                    const ull mlo = (aL & 1) ? 0xFFFFFFFF00000000ull : ~0ull;
                    const ull mhi = (bL & 1) ? 0x00000000FFFFFFFFull : ~0ull;
                    const ull* hp = &hrow[qs];
                    const ulonglong2* xp = xrow + (size_t)qs * 8;
                    if (qe == qs) {
                        ull h2 = *hp & (mlo & mhi);
                        ulonglong2 xv = *xp;
                        a0 = ffma2(h2, xv.x, a0); a1 = ffma2(h2, xv.y, a1);
                    } else {
                        {   // first (masked)
                            ull h2 = *hp & mlo;
                            ulonglong2 xv = *xp;
                            a0 = ffma2(h2, xv.x, a0); a1 = ffma2(h2, xv.y, a1);
                            hp++; xp += 8;
                        }
                        int q = qs + 1;
                        if ((q & 1) && q < qe) {       // align to even q
                            ull h2 = *hp;
                            ulonglong2 xv = *xp;
                            a0 = ffma2(h2, xv.x, a0); a1 = ffma2(h2, xv.y, a1);
                            hp++; xp += 8; q++;
                        }
                        #pragma unroll 2
                        for (; q + 1 < qe; q += 2) {   // two pairs: LDS.128 on h
                            ulonglong2 h4 = *(const ulonglong2*)hp;
                            ulonglong2 xv0 = xp[0];
                            ulonglong2 xv1 = xp[8];
                            a0 = ffma2(h4.x, xv0.x, a0); a1 = ffma2(h4.x, xv0.y, a1);
                            a0 = ffma2(h4.y, xv1.x, a0); a1 = ffma2(h4.y, xv1.y, a1);
                            hp += 2; xp += 16;
                        }
                        if (q < qe) {
                            ull h2 = *hp;
                            ulonglong2 xv = *xp;
                            a0 = ffma2(h2, xv.x, a0); a1 = ffma2(h2, xv.y, a1);
                            hp++; xp += 8; q++;
                        }
                        {   // last (masked)
                            ull h2 = *hp & mhi;
                            ulonglong2 xv = *xp;
                            a0 = ffma2(h2, xv.x, a0); a1 = ffma2(h2, xv.y, a1);
                        }
                    }
                    if (tid < 16) {   // S accumulation (i = tid)
                        const int ip = tid >> 1, iw = tid & 1;
                        const ull* xrp = (const ull*)&SM->Xq[qs][ip] + iw;
                        ull x2 = *xrp & mlo;
                        if (qe == qs) x2 &= mhi;
                        aS = add2(aS, x2);
                        xrp += 16;
                        for (int q = qs + 1; q < qe; q++, xrp += 16)
                            aS = add2(aS, *xrp);
                        if (qe > qs) aS = add2(aS, *xrp & mhi);
                    }
                }
                if (bk > base && bk <= cend && bk > ak) {   // segment ends here
                    float2 fa = unpk(a0), fb = unpk(a1);
                    SM->Mbuf[k][tid] = pk2(fa.x + fa.y, fb.x + fb.y);
                    a0 = 0ull; a1 = 0ull;
                    if (tid < 16) {
                        float2 fs = unpk(aS);
                        ((float*)SM->Sb2)[k * 16 + tid] = fs.x + fs.y;
                        aS = 0ull;
                    }
                }
            }
            __syncthreads();
        }

        // ---- GEMM: 8-way k-split, each warp covers all 8 nodes ----
        {
            const int w = tid >> 5, lane = tid & 31;
            const int o = lane & 15, gh = lane >> 4;     // gh: node half
            ull s0g = 0ull, s1g = 0ull, s2g = 0ull, s3g = 0ull;
            const ulonglong2* wp = &W2Q[w * 16][o];
            const ull* mb0 = &SM->Mbuf[gh * 4 + 0][2 * (w * 16)];
            const ull* mb1 = &SM->Mbuf[gh * 4 + 1][2 * (w * 16)];
            const ull* mb2 = &SM->Mbuf[gh * 4 + 2][2 * (w * 16)];
            const ull* mb3 = &SM->Mbuf[gh * 4 + 3][2 * (w * 16)];
            #pragma unroll 4
            for (int it = 0; it < 16; it++) {
                ulonglong2 w2 = __ldg(wp); wp += 16;
                ulonglong2 m0 = *(const ulonglong2*)mb0; mb0 += 2;
                ulonglong2 m1 = *(const ulonglong2*)mb1; mb1 += 2;
                ulonglong2 m2 = *(const ulonglong2*)mb2; mb2 += 2;
                ulonglong2 m3 = *(const ulonglong2*)mb3; mb3 += 2;
                s0g = ffma2(m0.x, w2.x, s0g); s0g = ffma2(m0.y, w2.y, s0g);
                s1g = ffma2(m1.x, w2.x, s1g); s1g = ffma2(m1.y, w2.y, s1g);
                s2g = ffma2(m2.x, w2.x, s2g); s2g = ffma2(m2.y, w2.y, s2g);
                s3g = ffma2(m3.x, w2.x, s3g); s3g = ffma2(m3.y, w2.y, s3g);
            }
            ull* Gred = &SM->Hp[0][0];       // Hp dead after last chunk
            Gred[w * 128 + (gh * 4 + 0) * 16 + o] = s0g;
            Gred[w * 128 + (gh * 4 + 1) * 16 + o] = s1g;
            Gred[w * 128 + (gh * 4 + 2) * 16 + o] = s2g;
            Gred[w * 128 + (gh * 4 + 3) * 16 + o] = s3g;
        }
        __syncthreads();
        if (tid < 128) {
            const int g = tid >> 4, o = tid & 15;
            const ull* Gred = &SM->Hp[0][0];
            ull s = Gred[g * 16 + o];
            #pragma unroll
            for (int w = 1; w < 8; w++) s = add2(s, Gred[w * 128 + g * 16 + o]);
            #pragma unroll
            for (int pp = 0; pp < 8; pp++)
                s = ffma2(SM->Sb2[g][pp], __ldg(&b2P[0][0] + pp * 16 + o), s);
            if (g < nn) {
                float2 f = unpk(s);
                float d = __ldg(degs + t0 + g);
                out[(t0 + g) * 16 + o] = (d > 0.f) ? (f.x + f.y) / d : 0.f;
            }
        }
    } else {
        // ================= node-0 slice blocks =================
        const int e0e = (int)__ldg(degs);   // node 0 owns edges [0, degs[0])
        ull a0 = 0ull, a1 = 0ull, aS = 0ull;
        __syncthreads();

        for (int base = bx * CH; base < e0e; base += EX * CH) {
            const int c = min(CH, e0e - base);
            const int cpad = (c + 1) & ~1;
            const int qn = cpad >> 1;

            for (int k = tid; k < cpad * EDGE_F; k += 256) {
                int e = k / EDGE_F, f = k - e * EDGE_F;
                EFf[f * (2 * EFS) + e] =
                    (e < c) ? __ldg(ef + (size_t)base * EDGE_F + k) : 0.f;
            }
            for (int t = tid; t < cpad * 4; t += 256) {
                int e = t >> 2, r = t & 3;
                float4 v = make_float4(0.f, 0.f, 0.f, 0.f);
                if (e < c) {
                    int src = __ldg(idxn + base + e);
                    v = __ldg((const float4*)x + (size_t)src * 4 + r);
                }
                int q = e >> 1, hh = e & 1;
                float* c0 = (float*)&SM->Xq[q][2 * r];
                float* c1 = (float*)&SM->Xq[q][2 * r + 1];
                c0[hh]     = v.x;
                c0[2 + hh] = v.y;
                c1[hh]     = v.z;
                c1[2 + hh] = v.w;
            }
            __syncthreads();

            H_COMPUTE();
            __syncthreads();

            {
                const ull* hp = hrow;
                const ulonglong2* xp = xrow;
                int q = 0;
                #pragma unroll 2
                for (; q + 1 < qn; q += 2) {
                    ulonglong2 h4 = *(const ulonglong2*)hp;
                    ulonglong2 xv0 = xp[0];
                    ulonglong2 xv1 = xp[8];
                    a0 = ffma2(h4.x, xv0.x, a0); a1 = ffma2(h4.x, xv0.y, a1);
                    a0 = ffma2(h4.y, xv1.x, a0); a1 = ffma2(h4.y, xv1.y, a1);
                    hp += 2; xp += 16;
                }
                if (q < qn) {
                    ull h2 = *hp;
                    ulonglong2 xv = *xp;
                    a0 = ffma2(h2, xv.x, a0); a1 = ffma2(h2, xv.y, a1);
                }
            }
            if (tid < 16) {
                const int ip = tid >> 1, iw = tid & 1;
                const ull* xrp = (const ull*)&SM->Xq[0][ip] + iw;
                for (int q = 0; q < qn; q++, xrp += 16)
                    aS = add2(aS, *xrp);
            }
            __syncthreads();
        }
        float2 fa = unpk(a0), fb = unpk(a1);
        Mg0x[bx][tid] = pk2(fa.x + fa.y, fb.x + fb.y);
        if (tid < 16) {
            float2 fs = unpk(aS);
            Sg0x[bx][tid] = fs.x + fs.y;
        }
    }
}

// ---------------------------------------------------------------------------
__global__ void __launch_bounds__(256)
node0_kernel(const float* __restrict__ degs, float* __restrict__ out)
{
    __shared__ float wred[8][16];
    __shared__ float ssum[16];
    int tid = threadIdx.x, lane = tid & 31, w = tid >> 5;

    ull m = Mg0x[0][tid];
    #pragma unroll
    for (int e2 = 1; e2 < EX; e2++) m = add2(m, Mg0x[e2][tid]);
    if (tid < 16) {
        float s = 0.f;
        #pragma unroll
        for (int e2 = 0; e2 < EX; e2++) s += Sg0x[e2][tid];
        ssum[tid] = s;
    }
    float po[16];
    #pragma unroll
    for (int o = 0; o < 16; o++) {
        ull wk = ((const ull*)&W2Q[tid >> 1][o])[tid & 1];
        ull t2 = ffma2(m, wk, 0ull);
        float2 f = unpk(t2);
        po[o] = f.x + f.y;
    }
    #pragma unroll
    for (int o = 0; o < 16; o++)
        #pragma unroll
        for (int off = 16; off; off >>= 1)
            po[o] += __shfl_down_sync(0xffffffffu, po[o], off);
    if (lane == 0)
        #pragma unroll
        for (int o = 0; o < 16; o++) wred[w][o] = po[o];
    __syncthreads();
    if (tid < 16) {
        float t = 0.f;
        #pragma unroll
        for (int w2 = 0; w2 < 8; w2++) t += wred[w2][tid];
        float s2 = 0.f;
        #pragma unroll
        for (int pp = 0; pp < 8; pp++) {
            ull q = ffma2(pk2(ssum[2 * pp], ssum[2 * pp + 1]), b2P[pp][tid], 0ull);
            float2 f = unpk(q);
            s2 += f.x + f.y;
        }
        float d = __ldg(degs);
        out[tid] = (d > 0.f) ? (t + s2) / d : 0.f;
    }
}

// ---------------------------------------------------------------------------
extern "C" void kernel_launch(void* const* d_in, const int* in_sizes, int n_in,
                              void* d_out, int out_size)
{
    const float* x    = (const float*)d_in[0];
    const float* ef   = (const float*)d_in[1];
    const float* W1   = (const float*)d_in[2];
    const float* b1   = (const float*)d_in[3];
    const float* W2   = (const float*)d_in[4];
    const float* b2   = (const float*)d_in[5];
    const int*   idxn = (const int*)d_in[6];
    const float* degs = (const float*)d_in[8];
    float* out = (float*)d_out;

    const int E = in_sizes[6];
    static int smem_set = 0;
    if (!smem_set) {
        cudaFuncSetAttribute(fused_kernel,
                             cudaFuncAttributeMaxDynamicSharedMemorySize,
                             (int)sizeof(SmemT));
        smem_set = 1;
    }

    scan1_kernel<<<SCAN_NB + 1, SCAN_B>>>(degs, W2, b2);
    scan2_kernel<<<1, 128>>>();
    fused_kernel<<<EX + NBLK, 256, sizeof(SmemT)>>>(x, ef, W1, b1, idxn, degs, out, E);
    node0_kernel<<<1, 256>>>(degs, out);
}

// round 12
// speedup vs baseline: 1.0734x; 1.0492x over previous
#include <cuda_runtime.h>

#define N_NODES 50000
#define EDGE_F  13
#define HID     32
#define NB      8            // nodes per main block (deg<=32 -> <=256 edges)
#define CH      128          // edges per staging chunk
#define PAIRS   64           // CH/2
#define EFS     66           // EFp/Hp row stride in ull (16B-aligned, even)
#define EX      16           // node-0 slice blocks (first in grid)
#define NBLK    ((N_NODES + NB - 1) / NB)   // 6250
#define SCAN_B  512
#define SCAN_NB ((N_NODES + SCAN_B - 1) / SCAN_B)   // 98

typedef unsigned long long ull;

__device__ ulonglong2 W2Q[128][16];   // k-paired packed W2 (8 KB, L1-hot)
__device__ ull        b2P[8][16];
__device__ ull        Mg0x[EX][256];
__device__ float      Sg0x[EX][16];
__device__ int        StartsG[N_NODES];
__device__ int        PsumG[128];
__device__ int        OffG[128];
__device__ int        Ctr0;           // node-0 completion counter (self-resetting)

// ---- packed fp32x2 helpers (sm_103a FFMA2, PTX-only) ----
__device__ __forceinline__ ull pk2(float a, float b) {
    ull r; asm("mov.b64 %0, {%1,%2};" : "=l"(r) : "f"(a), "f"(b)); return r;
}
__device__ __forceinline__ ull ffma2(ull a, ull b, ull c) {
    ull d; asm("fma.rn.f32x2 %0, %1, %2, %3;" : "=l"(d) : "l"(a), "l"(b), "l"(c)); return d;
}
__device__ __forceinline__ ull add2(ull a, ull b) {
    ull d; asm("add.rn.f32x2 %0, %1, %2;" : "=l"(d) : "l"(a), "l"(b)); return d;
}
__device__ __forceinline__ float2 unpk(ull a) {
    float2 f; asm("mov.b64 {%0,%1}, %2;" : "=f"(f.x), "=f"(f.y) : "l"(a)); return f;
}

// ---------------------------------------------------------------------------
// scan1 + pack fused: blocks [0, SCAN_NB) scan degs; block SCAN_NB packs W2/b2
// ---------------------------------------------------------------------------
__global__ void scan1_kernel(const float* __restrict__ degs,
                             const float* __restrict__ W2,
                             const float* __restrict__ b2)
{
    if (blockIdx.x == SCAN_NB) {
        int tid = threadIdx.x;
        for (int t = tid; t < 128 * 16; t += SCAN_B) {
            int k2 = t >> 4, o = t & 15;
            int k0 = 2 * k2, k1 = 2 * k2 + 1;
            int j0 = k0 >> 3, p0 = k0 & 7;
            int j1 = k1 >> 3, p1 = k1 & 7;
            ulonglong2 v;
            v.x = pk2(__ldg(W2 + j0 * 256 + 2 * p0 * 16 + o),
                      __ldg(W2 + j0 * 256 + (2 * p0 + 1) * 16 + o));
            v.y = pk2(__ldg(W2 + j1 * 256 + 2 * p1 * 16 + o),
                      __ldg(W2 + j1 * 256 + (2 * p1 + 1) * 16 + o));
            W2Q[k2][o] = v;
        }
        if (tid < 128) {
            int pp = tid >> 4, o = tid & 15;
            b2P[pp][o] = pk2(__ldg(b2 + 2 * pp * 16 + o),
                             __ldg(b2 + (2 * pp + 1) * 16 + o));
        }
        return;
    }
    __shared__ int s[SCAN_B];
    int b = blockIdx.x, t = threadIdx.x, n = b * SCAN_B + t;
    int d = (n < N_NODES) ? (int)degs[n] : 0;
    s[t] = d;
    for (int off = 1; off < SCAN_B; off <<= 1) {
        __syncthreads();
        int v = (t >= off) ? s[t - off] : 0;
        __syncthreads();
        s[t] += v;
    }
    if (n < N_NODES) StartsG[n] = s[t] - d;     // exclusive
    if (t == SCAN_B - 1) PsumG[b] = s[t];
}

__global__ void scan2_kernel()
{
    __shared__ int s[128];
    int t = threadIdx.x;
    s[t] = (t < SCAN_NB) ? PsumG[t] : 0;
    __syncthreads();
    if (t == 0) {
        int acc = 0;
        for (int i = 0; i < SCAN_NB; i++) { int v = s[i]; s[i] = acc; acc += v; }
    }
    __syncthreads();
    if (t < SCAN_NB) OffG[t] = s[t];
}

// ---------------------------------------------------------------------------
struct __align__(16) SmemT {
    ulonglong2 Xq[PAIRS][8];      // 8.0 KB  x pairs, plain [q][p]
    ull Mbuf[NB][260];            // 16.6 KB (16B-aligned rows)
    ull Hp[HID][EFS];             // 16.9 KB; GEMM partials + node0 scratch alias
    ull EFp[EDGE_F][EFS];         // 6.9 KB
    ull W1s[EDGE_F][HID];         // 3.3 KB packed {w,w}
    ull b1s[HID];
    ull Sb2[NB][8];
    int sb[NB + 4];
};                                // ~52.5 KB -> 4 blocks/SM

// h-compute: one 8-pair group per thread (qb = tid>>5, jj = tid&31).
#define H_COMPUTE()                                                        \
    {                                                                      \
        const int qb = tid >> 5, jj = tid & 31;                            \
        ull hh0, hh1, hh2, hh3, hh4, hh5, hh6, hh7;                        \
        { ull bb = SM->b1s[jj];                                            \
          hh0 = bb; hh1 = bb; hh2 = bb; hh3 = bb;                          \
          hh4 = bb; hh5 = bb; hh6 = bb; hh7 = bb; }                        \
        _Pragma("unroll")                                                  \
        for (int f = 0; f < EDGE_F; f++) {                                 \
            ull w = SM->W1s[f][jj];                                        \
            const ull* efr = &SM->EFp[f][qb * 8];                          \
            ulonglong2 eA = *(const ulonglong2*)(efr);                     \
            ulonglong2 eB = *(const ulonglong2*)(efr + 2);                 \
            hh0 = ffma2(eA.x, w, hh0); hh1 = ffma2(eA.y, w, hh1);          \
            hh2 = ffma2(eB.x, w, hh2); hh3 = ffma2(eB.y, w, hh3);          \
            ulonglong2 eC = *(const ulonglong2*)(efr + 4);                 \
            ulonglong2 eD = *(const ulonglong2*)(efr + 6);                 \
            hh4 = ffma2(eC.x, w, hh4); hh5 = ffma2(eC.y, w, hh5);          \
            hh6 = ffma2(eD.x, w, hh6); hh7 = ffma2(eD.y, w, hh7);          \
        }                                                                  \
        ull* hdst = &SM->Hp[jj][qb * 8];                                   \
        float2 fA, fB; ulonglong2 ov;                                      \
        fA = unpk(hh0); fB = unpk(hh1);                                    \
        ov.x = pk2(fmaxf(fA.x, 0.f), fmaxf(fA.y, 0.f));                    \
        ov.y = pk2(fmaxf(fB.x, 0.f), fmaxf(fB.y, 0.f));                    \
        *(ulonglong2*)(hdst) = ov;                                         \
        fA = unpk(hh2); fB = unpk(hh3);                                    \
        ov.x = pk2(fmaxf(fA.x, 0.f), fmaxf(fA.y, 0.f));                    \
        ov.y = pk2(fmaxf(fB.x, 0.f), fmaxf(fB.y, 0.f));                    \
        *(ulonglong2*)(hdst + 2) = ov;                                     \
        fA = unpk(hh4); fB = unpk(hh5);                                    \
        ov.x = pk2(fmaxf(fA.x, 0.f), fmaxf(fA.y, 0.f));                    \
        ov.y = pk2(fmaxf(fB.x, 0.f), fmaxf(fB.y, 0.f));                    \
        *(ulonglong2*)(hdst + 4) = ov;                                     \
        fA = unpk(hh6); fB = unpk(hh7);                                    \
        ov.x = pk2(fmaxf(fA.x, 0.f), fmaxf(fA.y, 0.f));                    \
        ov.y = pk2(fmaxf(fB.x, 0.f), fmaxf(fB.y, 0.f));                    \
        *(ulonglong2*)(hdst + 6) = ov;                                     \
    }

__global__ void __launch_bounds__(256, 4)
fused_kernel(const float* __restrict__ x,
             const float* __restrict__ ef,
             const float* __restrict__ W1,
             const float* __restrict__ b1,
             const int*   __restrict__ idxn,
             const float* __restrict__ degs,
             float* __restrict__ out,
             int E)
{
    extern __shared__ char smem_raw[];
    SmemT* SM = (SmemT*)smem_raw;
    const int tid = threadIdx.x;
    const int bx  = blockIdx.x;
    const int j = tid >> 3, p = tid & 7;
    const int wS = tid >> 5, laneS = tid & 31;   // S-phase: warp wS owns node wS

    for (int t = tid; t < EDGE_F * HID; t += 256) {
        float w = __ldg(W1 + t);
        SM->W1s[t / HID][t % HID] = pk2(w, w);
    }
    if (tid < HID) { float bb = __ldg(b1 + tid); SM->b1s[tid] = pk2(bb, bb); }

    float* EFf = (float*)SM->EFp;       // row stride 2*EFS floats
    const ull* hrow = SM->Hp[j];
    const ulonglong2* xrow = &SM->Xq[0][p];    // advance by 8 per q

    if (bx >= EX) {
        // ================= main blocks: 8 nodes =================
        const int mb = bx - EX;
        const int t0 = (mb == 0) ? 1 : mb * NB;     // node 0 excluded
        int t1 = mb * NB + NB; if (t1 > N_NODES) t1 = N_NODES;
        const int nn = t1 - t0;

        if (tid <= NB) {
            int target = t0 + tid; if (target > t1) target = t1;
            SM->sb[tid] = (target >= N_NODES) ? E
                          : (StartsG[target] + OffG[target >> 9]);
        }
        __syncthreads();

        const int es = SM->sb[0];
        const int ee = SM->sb[NB];
        ull a0 = 0ull, a1 = 0ull, aS = 0ull;

        for (int base = es; base < ee; base += CH) {
            const int c = min(CH, ee - base);
            const int cpad = (c + 1) & ~1;

            // ---- stage ef (zero-padded to cpad) ----
            for (int k = tid; k < cpad * EDGE_F; k += 256) {
                int e = k / EDGE_F, f = k - e * EDGE_F;
                EFf[f * (2 * EFS) + e] =
                    (e < c) ? __ldg(ef + (size_t)base * EDGE_F + k) : 0.f;
            }
            // ---- stage x gather ----
            for (int t = tid; t < cpad * 4; t += 256) {
                int e = t >> 2, r = t & 3;
                float4 v = make_float4(0.f, 0.f, 0.f, 0.f);
                if (e < c) {
                    int src = __ldg(idxn + base + e);
                    v = __ldg((const float4*)x + (size_t)src * 4 + r);
                }
                int q = e >> 1, hh = e & 1;
                float* c0 = (float*)&SM->Xq[q][2 * r];
                float* c1 = (float*)&SM->Xq[q][2 * r + 1];
                c0[hh]     = v.x;
                c0[2 + hh] = v.y;
                c1[hh]     = v.z;
                c1[2 + hh] = v.w;
            }
            __syncthreads();

            // ---- h: 8-pair group per thread ----
            H_COMPUTE();
            __syncthreads();

            const int cend = base + c;
            // ---- per-node masked rank-1 accumulation (no S in this loop) ----
            #pragma unroll 1
            for (int k = 0; k < NB; k++) {
                const int ak = SM->sb[k], bk = SM->sb[k + 1];
                int aL = ak - base; if (aL < 0) aL = 0;
                int bL = bk - base; if (bL > c) bL = c;
                if (bL > aL) {
                    const int qs = aL >> 1, qe = (bL - 1) >> 1;
                    const ull mlo = (aL & 1) ? 0xFFFFFFFF00000000ull : ~0ull;
                    const ull mhi = (bL & 1) ? 0x00000000FFFFFFFFull : ~0ull;
                    const ull* hp = &hrow[qs];
                    const ulonglong2* xp = xrow + (size_t)qs * 8;
                    if (qe == qs) {
                        ull h2 = *hp & (mlo & mhi);
                        ulonglong2 xv = *xp;
                        a0 = ffma2(h2, xv.x, a0); a1 = ffma2(h2, xv.y, a1);
                    } else {
                        {   // first (masked)
                            ull h2 = *hp & mlo;
                            ulonglong2 xv = *xp;
                            a0 = ffma2(h2, xv.x, a0); a1 = ffma2(h2, xv.y, a1);
                            hp++; xp += 8;
                        }
                        int q = qs + 1;
                        if ((q & 1) && q < qe) {       // align to even q
                            ull h2 = *hp;
                            ulonglong2 xv = *xp;
                            a0 = ffma2(h2, xv.x, a0); a1 = ffma2(h2, xv.y, a1);
                            hp++; xp += 8; q++;
                        }
                        #pragma unroll 2
                        for (; q + 1 < qe; q += 2) {   // two pairs: LDS.128 on h
                            ulonglong2 h4 = *(const ulonglong2*)hp;
                            ulonglong2 xv0 = xp[0];
                            ulonglong2 xv1 = xp[8];
                            a0 = ffma2(h4.x, xv0.x, a0); a1 = ffma2(h4.x, xv0.y, a1);
                            a0 = ffma2(h4.y, xv1.x, a0); a1 = ffma2(h4.y, xv1.y, a1);
                            hp += 2; xp += 16;
                        }
                        if (q < qe) {
                            ull h2 = *hp;
                            ulonglong2 xv = *xp;
                            a0 = ffma2(h2, xv.x, a0); a1 = ffma2(h2, xv.y, a1);
                            hp++; xp += 8; q++;
                        }
                        {   // last (masked)
                            ull h2 = *hp & mhi;
                            ulonglong2 xv = *xp;
                            a0 = ffma2(h2, xv.x, a0); a1 = ffma2(h2, xv.y, a1);
                        }
                    }
                }
                if (bk > base && bk <= cend && bk > ak) {   // segment ends here
                    float2 fa = unpk(a0), fb = unpk(a1);
                    SM->Mbuf[k][tid] = pk2(fa.x + fa.y, fb.x + fb.y);
                    a0 = 0ull; a1 = 0ull;
                }
            }

            // ---- S phase: warp wS owns node wS (lanes 0-15, i = laneS) ----
            if (laneS < 16) {
                const int ak = SM->sb[wS], bk = SM->sb[wS + 1];
                int aL = ak - base; if (aL < 0) aL = 0;
                int bL = bk - base; if (bL > c) bL = c;
                if (bL > aL) {
                    const int qs = aL >> 1, qe = (bL - 1) >> 1;
                    const ull mlo = (aL & 1) ? 0xFFFFFFFF00000000ull : ~0ull;
                    const ull mhi = (bL & 1) ? 0x00000000FFFFFFFFull : ~0ull;
                    const ull* xrp = (const ull*)&SM->Xq[qs][laneS >> 1] + (laneS & 1);
                    ull x2 = *xrp & mlo;
                    if (qe == qs) x2 &= mhi;
                    aS = add2(aS, x2);
                    xrp += 16;
                    for (int q = qs + 1; q < qe; q++, xrp += 16)
                        aS = add2(aS, *xrp);
                    if (qe > qs) aS = add2(aS, *xrp & mhi);
                }
                if (bk > base && bk <= cend && bk > ak) {
                    float2 fs = unpk(aS);
                    ((float*)SM->Sb2)[wS * 16 + laneS] = fs.x + fs.y;
                    aS = 0ull;
                }
            }
            __syncthreads();
        }

        // ---- GEMM: 8-way k-split, each warp covers all 8 nodes ----
        {
            const int w = tid >> 5, lane = tid & 31;
            const int o = lane & 15, gh = lane >> 4;     // gh: node half
            ull s0g = 0ull, s1g = 0ull, s2g = 0ull, s3g = 0ull;
            const ulonglong2* wp = &W2Q[w * 16][o];
            const ull* mb0 = &SM->Mbuf[gh * 4 + 0][2 * (w * 16)];
            const ull* mb1 = &SM->Mbuf[gh * 4 + 1][2 * (w * 16)];
            const ull* mb2 = &SM->Mbuf[gh * 4 + 2][2 * (w * 16)];
            const ull* mb3 = &SM->Mbuf[gh * 4 + 3][2 * (w * 16)];
            #pragma unroll 4
            for (int it = 0; it < 16; it++) {
                ulonglong2 w2 = __ldg(wp); wp += 16;
                ulonglong2 m0 = *(const ulonglong2*)mb0; mb0 += 2;
                ulonglong2 m1 = *(const ulonglong2*)mb1; mb1 += 2;
                ulonglong2 m2 = *(const ulonglong2*)mb2; mb2 += 2;
                ulonglong2 m3 = *(const ulonglong2*)mb3; mb3 += 2;
                s0g = ffma2(m0.x, w2.x, s0g); s0g = ffma2(m0.y, w2.y, s0g);
                s1g = ffma2(m1.x, w2.x, s1g); s1g = ffma2(m1.y, w2.y, s1g);
                s2g = ffma2(m2.x, w2.x, s2g); s2g = ffma2(m2.y, w2.y, s2g);
                s3g = ffma2(m3.x, w2.x, s3g); s3g = ffma2(m3.y, w2.y, s3g);
            }
            ull* Gred = &SM->Hp[0][0];       // Hp dead after last chunk
            Gred[w * 128 + (gh * 4 + 0) * 16 + o] = s0g;
            Gred[w * 128 + (gh * 4 + 1) * 16 + o] = s1g;
            Gred[w * 128 + (gh * 4 + 2) * 16 + o] = s2g;
            Gred[w * 128 + (gh * 4 + 3) * 16 + o] = s3g;
        }
        __syncthreads();
        if (tid < 128) {
            const int g = tid >> 4, o = tid & 15;
            const ull* Gred = &SM->Hp[0][0];
            ull s = Gred[g * 16 + o];
            #pragma unroll
            for (int w = 1; w < 8; w++) s = add2(s, Gred[w * 128 + g * 16 + o]);
            #pragma unroll
            for (int pp = 0; pp < 8; pp++)
                s = ffma2(SM->Sb2[g][pp], __ldg(&b2P[0][0] + pp * 16 + o), s);
            if (g < nn) {
                float2 f = unpk(s);
                float d = __ldg(degs + t0 + g);
                out[(t0 + g) * 16 + o] = (d > 0.f) ? (f.x + f.y) / d : 0.f;
            }
        }
    } else {
        // ================= node-0 slice blocks =================
        const int e0e = (int)__ldg(degs);   // node 0 owns edges [0, degs[0])
        ull a0 = 0ull, a1 = 0ull, aS = 0ull;
        __syncthreads();

        for (int base = bx * CH; base < e0e; base += EX * CH) {
            const int c = min(CH, e0e - base);
            const int cpad = (c + 1) & ~1;
            const int qn = cpad >> 1;

            for (int k = tid; k < cpad * EDGE_F; k += 256) {
                int e = k / EDGE_F, f = k - e * EDGE_F;
                EFf[f * (2 * EFS) + e] =
                    (e < c) ? __ldg(ef + (size_t)base * EDGE_F + k) : 0.f;
            }
            for (int t = tid; t < cpad * 4; t += 256) {
                int e = t >> 2, r = t & 3;
                float4 v = make_float4(0.f, 0.f, 0.f, 0.f);
                if (e < c) {
                    int src = __ldg(idxn + base + e);
                    v = __ldg((const float4*)x + (size_t)src * 4 + r);
                }
                int q = e >> 1, hh = e & 1;
                float* c0 = (float*)&SM->Xq[q][2 * r];
                float* c1 = (float*)&SM->Xq[q][2 * r + 1];
                c0[hh]     = v.x;
                c0[2 + hh] = v.y;
                c1[hh]     = v.z;
                c1[2 + hh] = v.w;
            }
            __syncthreads();

            H_COMPUTE();
            __syncthreads();

            {
                const ull* hp = hrow;
                const ulonglong2* xp = xrow;
                int q = 0;
                #pragma unroll 2
                for (; q + 1 < qn; q += 2) {
                    ulonglong2 h4 = *(const ulonglong2*)hp;
                    ulonglong2 xv0 = xp[0];
                    ulonglong2 xv1 = xp[8];
                    a0 = ffma2(h4.x, xv0.x, a0); a1 = ffma2(h4.x, xv0.y, a1);
                    a0 = ffma2(h4.y, xv1.x, a0); a1 = ffma2(h4.y, xv1.y, a1);
                    hp += 2; xp += 16;
                }
                if (q < qn) {
                    ull h2 = *hp;
                    ulonglong2 xv = *xp;
                    a0 = ffma2(h2, xv.x, a0); a1 = ffma2(h2, xv.y, a1);
                }
            }
            if (tid < 16) {
                const int ip = tid >> 1, iw = tid & 1;
                const ull* xrp = (const ull*)&SM->Xq[0][ip] + iw;
                for (int q = 0; q < qn; q++, xrp += 16)
                    aS = add2(aS, *xrp);
            }
            __syncthreads();
        }
        {
            float2 fa = unpk(a0), fb = unpk(a1);
            Mg0x[bx][tid] = pk2(fa.x + fa.y, fb.x + fb.y);
            if (tid < 16) {
                float2 fs = unpk(aS);
                Sg0x[bx][tid] = fs.x + fs.y;
            }
        }

        // ---- last-arriving EX block reduces node 0 (fixed order => deterministic) ----
        __threadfence();
        __syncthreads();
        if (tid == 0)
            SM->sb[0] = (atomicAdd(&Ctr0, 1) == EX - 1) ? 1 : 0;
        __syncthreads();
        if (SM->sb[0]) {
            __threadfence();
            float* wred = (float*)&SM->Mbuf[0][0];   // 8*16 floats scratch
            float* ssum = wred + 128;                // 16 floats
            const int lane = tid & 31, w = tid >> 5;

            ull m = Mg0x[0][tid];
            #pragma unroll
            for (int e2 = 1; e2 < EX; e2++) m = add2(m, Mg0x[e2][tid]);
            if (tid < 16) {
                float s = 0.f;
                #pragma unroll
                for (int e2 = 0; e2 < EX; e2++) s += Sg0x[e2][tid];
                ssum[tid] = s;
            }
            float po[16];
            #pragma unroll
            for (int o = 0; o < 16; o++) {
                ull wk = ((const ull*)&W2Q[tid >> 1][o])[tid & 1];
                ull t2 = ffma2(m, wk, 0ull);
                float2 f = unpk(t2);
                po[o] = f.x + f.y;
            }
            #pragma unroll
            for (int o = 0; o < 16; o++)
                #pragma unroll
                for (int off = 16; off; off >>= 1)
                    po[o] += __shfl_down_sync(0xffffffffu, po[o], off);
            if (lane == 0)
                #pragma unroll
                for (int o = 0; o < 16; o++) wred[w * 16 + o] = po[o];
            __syncthreads();
            if (tid < 16) {
                float t = 0.f;
                #pragma unroll
                for (int w2 = 0; w2 < 8; w2++) t += wred[w2 * 16 + tid];
                float s2 = 0.f;
                #pragma unroll
                for (int pp = 0; pp < 8; pp++) {
                    ull q = ffma2(pk2(ssum[2 * pp], ssum[2 * pp + 1]),
                                  b2P[pp][tid], 0ull);
                    float2 f = unpk(q);
                    s2 += f.x + f.y;
                }
                float d = __ldg(degs);
                out[tid] = (d > 0.f) ? (t + s2) / d : 0.f;
            }
            if (tid == 0) Ctr0 = 0;    // reset for next graph replay
        }
    }
}

// ---------------------------------------------------------------------------
extern "C" void kernel_launch(void* const* d_in, const int* in_sizes, int n_in,
                              void* d_out, int out_size)
{
    const float* x    = (const float*)d_in[0];
    const float* ef   = (const float*)d_in[1];
    const float* W1   = (const float*)d_in[2];
    const float* b1   = (const float*)d_in[3];
    const float* W2   = (const float*)d_in[4];
    const float* b2   = (const float*)d_in[5];
    const int*   idxn = (const int*)d_in[6];
    const float* degs = (const float*)d_in[8];
    float* out = (float*)d_out;

    const int E = in_sizes[6];
    static int smem_set = 0;
    if (!smem_set) {
        cudaFuncSetAttribute(fused_kernel,
                             cudaFuncAttributeMaxDynamicSharedMemorySize,
                             (int)sizeof(SmemT));
        smem_set = 1;
    }

    scan1_kernel<<<SCAN_NB + 1, SCAN_B>>>(degs, W2, b2);
    scan2_kernel<<<1, 128>>>();
    fused_kernel<<<EX + NBLK, 256, sizeof(SmemT)>>>(x, ef, W1, b1, idxn, degs, out, E);
}

// round 13
// speedup vs baseline: 1.1505x; 1.0718x over previous
#include <cuda_runtime.h>

#define N_NODES 50000
#define EDGE_F  13
#define HID     32
#define NB      8            // nodes per main block (deg<=32 -> <=256 edges)
#define CH      128          // edges per staging chunk
#define PAIRS   64           // CH/2
#define EFS     66           // EFp/Hp row stride in ull (16B-aligned, even)
#define EX      16           // node-0 slice blocks (first in grid)
#define NBLK    ((N_NODES + NB - 1) / NB)   // 6250
#define SCAN_B  512
#define SCAN_NB ((N_NODES + SCAN_B - 1) / SCAN_B)   // 98

typedef unsigned long long ull;

__device__ ulonglong2 W2Q[128][16];   // k-paired packed W2 (8 KB, L1-hot)
__device__ ull        b2P[8][16];
__device__ ull        Mg0x[EX][256];
__device__ float      Sg0x[EX][16];
__device__ int        StartsG[N_NODES];
__device__ int        PsumG[128];
__device__ int        OffG[128];
__device__ int        Ctr0;           // node-0 completion counter (self-resetting)
__device__ int        ScanCtr;        // scan completion counter (self-resetting)

// ---- packed fp32x2 helpers (sm_103a FFMA2, PTX-only) ----
__device__ __forceinline__ ull pk2(float a, float b) {
    ull r; asm("mov.b64 %0, {%1,%2};" : "=l"(r) : "f"(a), "f"(b)); return r;
}
__device__ __forceinline__ ull ffma2(ull a, ull b, ull c) {
    ull d; asm("fma.rn.f32x2 %0, %1, %2, %3;" : "=l"(d) : "l"(a), "l"(b), "l"(c)); return d;
}
__device__ __forceinline__ ull add2(ull a, ull b) {
    ull d; asm("add.rn.f32x2 %0, %1, %2;" : "=l"(d) : "l"(a), "l"(b)); return d;
}
__device__ __forceinline__ float2 unpk(ull a) {
    float2 f; asm("mov.b64 {%0,%1}, %2;" : "=f"(f.x), "=f"(f.y) : "l"(a)); return f;
}

// ---------------------------------------------------------------------------
// scan1 + pack + scan2 fused: blocks [0, SCAN_NB) scan degs (last finisher
// computes OffG); block SCAN_NB packs W2/b2.
// ---------------------------------------------------------------------------
__global__ void scan1_kernel(const float* __restrict__ degs,
                             const float* __restrict__ W2,
                             const float* __restrict__ b2)
{
    if (blockIdx.x == SCAN_NB) {
        int tid = threadIdx.x;
        for (int t = tid; t < 128 * 16; t += SCAN_B) {
            int k2 = t >> 4, o = t & 15;
            int k0 = 2 * k2, k1 = 2 * k2 + 1;
            int j0 = k0 >> 3, p0 = k0 & 7;
            int j1 = k1 >> 3, p1 = k1 & 7;
            ulonglong2 v;
            v.x = pk2(__ldg(W2 + j0 * 256 + 2 * p0 * 16 + o),
                      __ldg(W2 + j0 * 256 + (2 * p0 + 1) * 16 + o));
            v.y = pk2(__ldg(W2 + j1 * 256 + 2 * p1 * 16 + o),
                      __ldg(W2 + j1 * 256 + (2 * p1 + 1) * 16 + o));
            W2Q[k2][o] = v;
        }
        if (tid < 128) {
            int pp = tid >> 4, o = tid & 15;
            b2P[pp][o] = pk2(__ldg(b2 + 2 * pp * 16 + o),
                             __ldg(b2 + (2 * pp + 1) * 16 + o));
        }
        return;
    }
    __shared__ int s[SCAN_B];
    __shared__ int lastFlag;
    int b = blockIdx.x, t = threadIdx.x, n = b * SCAN_B + t;
    int d = (n < N_NODES) ? (int)degs[n] : 0;
    s[t] = d;
    for (int off = 1; off < SCAN_B; off <<= 1) {
        __syncthreads();
        int v = (t >= off) ? s[t - off] : 0;
        __syncthreads();
        s[t] += v;
    }
    if (n < N_NODES) StartsG[n] = s[t] - d;     // exclusive
    if (t == SCAN_B - 1) PsumG[b] = s[t];
    __threadfence();
    if (t == 0)
        lastFlag = (atomicAdd(&ScanCtr, 1) == SCAN_NB - 1) ? 1 : 0;
    __syncthreads();
    if (lastFlag) {
        __threadfence();
        if (t < 128) s[t] = (t < SCAN_NB) ? PsumG[t] : 0;
        __syncthreads();
        if (t == 0) {
            int acc = 0;
            for (int i = 0; i < SCAN_NB; i++) { int v = s[i]; s[i] = acc; acc += v; }
            ScanCtr = 0;               // reset for next graph replay
        }
        __syncthreads();
        if (t < SCAN_NB) OffG[t] = s[t];
    }
}

// ---------------------------------------------------------------------------
struct __align__(16) SmemT {
    ulonglong2 Xq[PAIRS][8];      // 8.0 KB  x pairs, plain [q][p]
    ull Mbuf[NB][260];            // 16.6 KB (16B-aligned rows)
    ull Hp[HID][EFS];             // 16.9 KB; GEMM partials + node0 scratch alias
    ull EFp[EDGE_F][EFS];         // 6.9 KB
    ull W1s[EDGE_F][HID];         // 3.3 KB packed {w,w}
    ull b1s[HID];
    ull Sb2[NB][8];
    int sb[NB + 4];
};                                // ~52.5 KB -> 4 blocks/SM

// h-compute: one 8-pair group per thread (qb = tid>>5, jj = tid&31),
// SKIPPED for groups entirely past the live pair count QN.
#define H_COMPUTE(QN)                                                      \
    {                                                                      \
        const int qb = tid >> 5, jj = tid & 31;                            \
        if (qb * 8 < (QN)) {                                               \
            ull hh0, hh1, hh2, hh3, hh4, hh5, hh6, hh7;                    \
            { ull bb = SM->b1s[jj];                                        \
              hh0 = bb; hh1 = bb; hh2 = bb; hh3 = bb;                      \
              hh4 = bb; hh5 = bb; hh6 = bb; hh7 = bb; }                    \
            _Pragma("unroll")                                              \
            for (int f = 0; f < EDGE_F; f++) {                             \
                ull w = SM->W1s[f][jj];                                    \
                const ull* efr = &SM->EFp[f][qb * 8];                      \
                ulonglong2 eA = *(const ulonglong2*)(efr);                 \
                ulonglong2 eB = *(const ulonglong2*)(efr + 2);             \
                hh0 = ffma2(eA.x, w, hh0); hh1 = ffma2(eA.y, w, hh1);      \
                hh2 = ffma2(eB.x, w, hh2); hh3 = ffma2(eB.y, w, hh3);      \
                ulonglong2 eC = *(const ulonglong2*)(efr + 4);             \
                ulonglong2 eD = *(const ulonglong2*)(efr + 6);             \
                hh4 = ffma2(eC.x, w, hh4); hh5 = ffma2(eC.y, w, hh5);      \
                hh6 = ffma2(eD.x, w, hh6); hh7 = ffma2(eD.y, w, hh7);      \
            }                                                              \
            ull* hdst = &SM->Hp[jj][qb * 8];                               \
            float2 fA, fB; ulonglong2 ov;                                  \
            fA = unpk(hh0); fB = unpk(hh1);                                \
            ov.x = pk2(fmaxf(fA.x, 0.f), fmaxf(fA.y, 0.f));                \
            ov.y = pk2(fmaxf(fB.x, 0.f), fmaxf(fB.y, 0.f));                \
            *(ulonglong2*)(hdst) = ov;                                     \
            fA = unpk(hh2); fB = unpk(hh3);                                \
            ov.x = pk2(fmaxf(fA.x, 0.f), fmaxf(fA.y, 0.f));                \
            ov.y = pk2(fmaxf(fB.x, 0.f), fmaxf(fB.y, 0.f));                \
            *(ulonglong2*)(hdst + 2) = ov;                                 \
            fA = unpk(hh4); fB = unpk(hh5);                                \
            ov.x = pk2(fmaxf(fA.x, 0.f), fmaxf(fA.y, 0.f));                \
            ov.y = pk2(fmaxf(fB.x, 0.f), fmaxf(fB.y, 0.f));                \
            *(ulonglong2*)(hdst + 4) = ov;                                 \
            fA = unpk(hh6); fB = unpk(hh7);                                \
            ov.x = pk2(fmaxf(fA.x, 0.f), fmaxf(fA.y, 0.f));                \
            ov.y = pk2(fmaxf(fB.x, 0.f), fmaxf(fB.y, 0.f));                \
            *(ulonglong2*)(hdst + 6) = ov;                                 \
        }                                                                  \
    }

__global__ void __launch_bounds__(256, 4)
fused_kernel(const float* __restrict__ x,
             const float* __restrict__ ef,
             const float* __restrict__ W1,
             const float* __restrict__ b1,
             const int*   __restrict__ idxn,
             const float* __restrict__ degs,
             float* __restrict__ out,
             int E)
{
    extern __shared__ char smem_raw[];
    SmemT* SM = (SmemT*)smem_raw;
    const int tid = threadIdx.x;
    const int bx  = blockIdx.x;
    const int j = tid >> 3, p = tid & 7;
    const int wS = tid >> 5, laneS = tid & 31;   // S-phase: warp wS owns node wS

    for (int t = tid; t < EDGE_F * HID; t += 256) {
        float w = __ldg(W1 + t);
        SM->W1s[t / HID][t % HID] = pk2(w, w);
    }
    if (tid < HID) { float bb = __ldg(b1 + tid); SM->b1s[tid] = pk2(bb, bb); }

    float* EFf = (float*)SM->EFp;       // row stride 2*EFS floats
    const ull* hrow = SM->Hp[j];
    const ulonglong2* xrow = &SM->Xq[0][p];    // advance by 8 per q

    if (bx >= EX) {
        // ================= main blocks: 8 nodes =================
        const int mb = bx - EX;
        const int t0 = (mb == 0) ? 1 : mb * NB;     // node 0 excluded
        int t1 = mb * NB + NB; if (t1 > N_NODES) t1 = N_NODES;
        const int nn = t1 - t0;

        if (tid <= NB) {
            int target = t0 + tid; if (target > t1) target = t1;
            SM->sb[tid] = (target >= N_NODES) ? E
                          : (StartsG[target] + OffG[target >> 9]);
        }
        __syncthreads();

        const int es = SM->sb[0];
        const int ee = SM->sb[NB];
        ull a0 = 0ull, a1 = 0ull, aS = 0ull;

        for (int base = es; base < ee; base += CH) {
            const int c = min(CH, ee - base);
            const int cpad = (c + 1) & ~1;
            const int qn = cpad >> 1;

            // ---- stage ef (zero-padded to cpad) ----
            for (int k = tid; k < cpad * EDGE_F; k += 256) {
                int e = k / EDGE_F, f = k - e * EDGE_F;
                EFf[f * (2 * EFS) + e] =
                    (e < c) ? __ldg(ef + (size_t)base * EDGE_F + k) : 0.f;
            }
            // ---- stage x gather ----
            for (int t = tid; t < cpad * 4; t += 256) {
                int e = t >> 2, r = t & 3;
                float4 v = make_float4(0.f, 0.f, 0.f, 0.f);
                if (e < c) {
                    int src = __ldg(idxn + base + e);
                    v = __ldg((const float4*)x + (size_t)src * 4 + r);
                }
                int q = e >> 1, hh = e & 1;
                float* c0 = (float*)&SM->Xq[q][2 * r];
                float* c1 = (float*)&SM->Xq[q][2 * r + 1];
                c0[hh]     = v.x;
                c0[2 + hh] = v.y;
                c1[hh]     = v.z;
                c1[2 + hh] = v.w;
            }
            __syncthreads();

            // ---- h: 8-pair group per thread, bounded by qn ----
            H_COMPUTE(qn);
            __syncthreads();

            const int cend = base + c;
            // ---- per-node masked rank-1 accumulation ----
            #pragma unroll 1
            for (int k = 0; k < NB; k++) {
                const int ak = SM->sb[k], bk = SM->sb[k + 1];
                int aL = ak - base; if (aL < 0) aL = 0;
                int bL = bk - base; if (bL > c) bL = c;
                if (bL > aL) {
                    const int qs = aL >> 1, qe = (bL - 1) >> 1;
                    const ull mlo = (aL & 1) ? 0xFFFFFFFF00000000ull : ~0ull;
                    const ull mhi = (bL & 1) ? 0x00000000FFFFFFFFull : ~0ull;
                    const ull* hp = &hrow[qs];
                    const ulonglong2* xp = xrow + (size_t)qs * 8;
                    if (qe == qs) {
                        ull h2 = *hp & (mlo & mhi);
                        ulonglong2 xv = *xp;
                        a0 = ffma2(h2, xv.x, a0); a1 = ffma2(h2, xv.y, a1);
                    } else {
                        {   // first (masked)
                            ull h2 = *hp & mlo;
                            ulonglong2 xv = *xp;
                            a0 = ffma2(h2, xv.x, a0); a1 = ffma2(h2, xv.y, a1);
                            hp++; xp += 8;
                        }
                        int q = qs + 1;
                        if ((q & 1) && q < qe) {       // align to even q
                            ull h2 = *hp;
                            ulonglong2 xv = *xp;
                            a0 = ffma2(h2, xv.x, a0); a1 = ffma2(h2, xv.y, a1);
                            hp++; xp += 8; q++;
                        }
                        #pragma unroll 2
                        for (; q + 1 < qe; q += 2) {   // two pairs: LDS.128 on h
                            ulonglong2 h4 = *(const ulonglong2*)hp;
                            ulonglong2 xv0 = xp[0];
                            ulonglong2 xv1 = xp[8];
                            a0 = ffma2(h4.x, xv0.x, a0); a1 = ffma2(h4.x, xv0.y, a1);
                            a0 = ffma2(h4.y, xv1.x, a0); a1 = ffma2(h4.y, xv1.y, a1);
                            hp += 2; xp += 16;
                        }
                        if (q < qe) {
                            ull h2 = *hp;
                            ulonglong2 xv = *xp;
                            a0 = ffma2(h2, xv.x, a0); a1 = ffma2(h2, xv.y, a1);
                            hp++; xp += 8; q++;
                        }
                        {   // last (masked)
                            ull h2 = *hp & mhi;
                            ulonglong2 xv = *xp;
                            a0 = ffma2(h2, xv.x, a0); a1 = ffma2(h2, xv.y, a1);
                        }
                    }
                }
                if (bk > base && bk <= cend && bk > ak) {   // segment ends here
                    float2 fa = unpk(a0), fb = unpk(a1);
                    SM->Mbuf[k][tid] = pk2(fa.x + fa.y, fb.x + fb.y);
                    a0 = 0ull; a1 = 0ull;
                }
            }

            // ---- S phase: warp wS owns node wS (lanes 0-15, i = laneS) ----
            if (laneS < 16) {
                const int ak = SM->sb[wS], bk = SM->sb[wS + 1];
                int aL = ak - base; if (aL < 0) aL = 0;
                int bL = bk - base; if (bL > c) bL = c;
                if (bL > aL) {
                    const int qs = aL >> 1, qe = (bL - 1) >> 1;
                    const ull mlo = (aL & 1) ? 0xFFFFFFFF00000000ull : ~0ull;
                    const ull mhi = (bL & 1) ? 0x00000000FFFFFFFFull : ~0ull;
                    const ull* xrp = (const ull*)&SM->Xq[qs][laneS >> 1] + (laneS & 1);
                    ull x2 = *xrp & mlo;
                    if (qe == qs) x2 &= mhi;
                    aS = add2(aS, x2);
                    xrp += 16;
                    for (int q = qs + 1; q < qe; q++, xrp += 16)
                        aS = add2(aS, *xrp);
                    if (qe > qs) aS = add2(aS, *xrp & mhi);
                }
                if (bk > base && bk <= cend && bk > ak) {
                    float2 fs = unpk(aS);
                    ((float*)SM->Sb2)[wS * 16 + laneS] = fs.x + fs.y;
                    aS = 0ull;
                }
            }
            __syncthreads();
        }

        // ---- GEMM: 8-way k-split, each warp covers all 8 nodes ----
        {
            const int w = tid >> 5, lane = tid & 31;
            const int o = lane & 15, gh = lane >> 4;     // gh: node half
            ull s0g = 0ull, s1g = 0ull, s2g = 0ull, s3g = 0ull;
            const ulonglong2* wp = &W2Q[w * 16][o];
            const ull* mb0 = &SM->Mbuf[gh * 4 + 0][2 * (w * 16)];
            const ull* mb1 = &SM->Mbuf[gh * 4 + 1][2 * (w * 16)];
            const ull* mb2 = &SM->Mbuf[gh * 4 + 2][2 * (w * 16)];
            const ull* mb3 = &SM->Mbuf[gh * 4 + 3][2 * (w * 16)];
            #pragma unroll 4
            for (int it = 0; it < 16; it++) {
                ulonglong2 w2 = __ldg(wp); wp += 16;
                ulonglong2 m0 = *(const ulonglong2*)mb0; mb0 += 2;
                ulonglong2 m1 = *(const ulonglong2*)mb1; mb1 += 2;
                ulonglong2 m2 = *(const ulonglong2*)mb2; mb2 += 2;
                ulonglong2 m3 = *(const ulonglong2*)mb3; mb3 += 2;
                s0g = ffma2(m0.x, w2.x, s0g); s0g = ffma2(m0.y, w2.y, s0g);
                s1g = ffma2(m1.x, w2.x, s1g); s1g = ffma2(m1.y, w2.y, s1g);
                s2g = ffma2(m2.x, w2.x, s2g); s2g = ffma2(m2.y, w2.y, s2g);
                s3g = ffma2(m3.x, w2.x, s3g); s3g = ffma2(m3.y, w2.y, s3g);
            }
            ull* Gred = &SM->Hp[0][0];       // Hp dead after last chunk
            Gred[w * 128 + (gh * 4 + 0) * 16 + o] = s0g;
            Gred[w * 128 + (gh * 4 + 1) * 16 + o] = s1g;
            Gred[w * 128 + (gh * 4 + 2) * 16 + o] = s2g;
            Gred[w * 128 + (gh * 4 + 3) * 16 + o] = s3g;
        }
        __syncthreads();
        if (tid < 128) {
            const int g = tid >> 4, o = tid & 15;
            const ull* Gred = &SM->Hp[0][0];
            ull s = Gred[g * 16 + o];
            #pragma unroll
            for (int w = 1; w < 8; w++) s = add2(s, Gred[w * 128 + g * 16 + o]);
            #pragma unroll
            for (int pp = 0; pp < 8; pp++)
                s = ffma2(SM->Sb2[g][pp], __ldg(&b2P[0][0] + pp * 16 + o), s);
            if (g < nn) {
                float2 f = unpk(s);
                float d = __ldg(degs + t0 + g);
                out[(t0 + g) * 16 + o] = (d > 0.f) ? (f.x + f.y) / d : 0.f;
            }
        }
    } else {
        // ================= node-0 slice blocks =================
        const int e0e = (int)__ldg(degs);   // node 0 owns edges [0, degs[0])
        ull a0 = 0ull, a1 = 0ull, aS = 0ull;
        __syncthreads();

        for (int base = bx * CH; base < e0e; base += EX * CH) {
            const int c = min(CH, e0e - base);
            const int cpad = (c + 1) & ~1;
            const int qn = cpad >> 1;

            for (int k = tid; k < cpad * EDGE_F; k += 256) {
                int e = k / EDGE_F, f = k - e * EDGE_F;
                EFf[f * (2 * EFS) + e] =
                    (e < c) ? __ldg(ef + (size_t)base * EDGE_F + k) : 0.f;
            }
            for (int t = tid; t < cpad * 4; t += 256) {
                int e = t >> 2, r = t & 3;
                float4 v = make_float4(0.f, 0.f, 0.f, 0.f);
                if (e < c) {
                    int src = __ldg(idxn + base + e);
                    v = __ldg((const float4*)x + (size_t)src * 4 + r);
                }
                int q = e >> 1, hh = e & 1;
                float* c0 = (float*)&SM->Xq[q][2 * r];
                float* c1 = (float*)&SM->Xq[q][2 * r + 1];
                c0[hh]     = v.x;
                c0[2 + hh] = v.y;
                c1[hh]     = v.z;
                c1[2 + hh] = v.w;
            }
            __syncthreads();

            H_COMPUTE(qn);
            __syncthreads();

            {
                const ull* hp = hrow;
                const ulonglong2* xp = xrow;
                int q = 0;
                #pragma unroll 2
                for (; q + 1 < qn; q += 2) {
                    ulonglong2 h4 = *(const ulonglong2*)hp;
                    ulonglong2 xv0 = xp[0];
                    ulonglong2 xv1 = xp[8];
                    a0 = ffma2(h4.x, xv0.x, a0); a1 = ffma2(h4.x, xv0.y, a1);
                    a0 = ffma2(h4.y, xv1.x, a0); a1 = ffma2(h4.y, xv1.y, a1);
                    hp += 2; xp += 16;
                }
                if (q < qn) {
                    ull h2 = *hp;
                    ulonglong2 xv = *xp;
                    a0 = ffma2(h2, xv.x, a0); a1 = ffma2(h2, xv.y, a1);
                }
            }
            if (tid < 16) {
                const int ip = tid >> 1, iw = tid & 1;
                const ull* xrp = (const ull*)&SM->Xq[0][ip] + iw;
                for (int q = 0; q < qn; q++, xrp += 16)
                    aS = add2(aS, *xrp);
            }
            __syncthreads();
        }
        {
            float2 fa = unpk(a0), fb = unpk(a1);
            Mg0x[bx][tid] = pk2(fa.x + fa.y, fb.x + fb.y);
            if (tid < 16) {
                float2 fs = unpk(aS);
                Sg0x[bx][tid] = fs.x + fs.y;
            }
        }

        // ---- last-arriving EX block reduces node 0 (fixed order => deterministic) ----
        __threadfence();
        __syncthreads();
        if (tid == 0)
            SM->sb[0] = (atomicAdd(&Ctr0, 1) == EX - 1) ? 1 : 0;
        __syncthreads();
        if (SM->sb[0]) {
            __threadfence();
            float* wred = (float*)&SM->Mbuf[0][0];   // 8*16 floats scratch
            float* ssum = wred + 128;                // 16 floats
            const int lane = tid & 31, w = tid >> 5;

            ull m = Mg0x[0][tid];
            #pragma unroll
            for (int e2 = 1; e2 < EX; e2++) m = add2(m, Mg0x[e2][tid]);
            if (tid < 16) {
                float s = 0.f;
                #pragma unroll
                for (int e2 = 0; e2 < EX; e2++) s += Sg0x[e2][tid];
                ssum[tid] = s;
            }
            float po[16];
            #pragma unroll
            for (int o = 0; o < 16; o++) {
                ull wk = ((const ull*)&W2Q[tid >> 1][o])[tid & 1];
                ull t2 = ffma2(m, wk, 0ull);
                float2 f = unpk(t2);
                po[o] = f.x + f.y;
            }
            #pragma unroll
            for (int o = 0; o < 16; o++)
                #pragma unroll
                for (int off = 16; off; off >>= 1)
                    po[o] += __shfl_down_sync(0xffffffffu, po[o], off);
            if (lane == 0)
                #pragma unroll
                for (int o = 0; o < 16; o++) wred[w * 16 + o] = po[o];
            __syncthreads();
            if (tid < 16) {
                float t = 0.f;
                #pragma unroll
                for (int w2 = 0; w2 < 8; w2++) t += wred[w2 * 16 + tid];
                float s2 = 0.f;
                #pragma unroll
                for (int pp = 0; pp < 8; pp++) {
                    ull q = ffma2(pk2(ssum[2 * pp], ssum[2 * pp + 1]),
                                  b2P[pp][tid], 0ull);
                    float2 f = unpk(q);
                    s2 += f.x + f.y;
                }
                float d = __ldg(degs);
                out[tid] = (d > 0.f) ? (t + s2) / d : 0.f;
            }
            if (tid == 0) Ctr0 = 0;    // reset for next graph replay
        }
    }
}

// ---------------------------------------------------------------------------
extern "C" void kernel_launch(void* const* d_in, const int* in_sizes, int n_in,
                              void* d_out, int out_size)
{
    const float* x    = (const float*)d_in[0];
    const float* ef   = (const float*)d_in[1];
    const float* W1   = (const float*)d_in[2];
    const float* b1   = (const float*)d_in[3];
    const float* W2   = (const float*)d_in[4];
    const float* b2   = (const float*)d_in[5];
    const int*   idxn = (const int*)d_in[6];
    const float* degs = (const float*)d_in[8];
    float* out = (float*)d_out;

    const int E = in_sizes[6];
    static int smem_set = 0;
    if (!smem_set) {
        cudaFuncSetAttribute(fused_kernel,
                             cudaFuncAttributeMaxDynamicSharedMemorySize,
                             (int)sizeof(SmemT));
        smem_set = 1;
    }

    scan1_kernel<<<SCAN_NB + 1, SCAN_B>>>(degs, W2, b2);
    fused_kernel<<<EX + NBLK, 256, sizeof(SmemT)>>>(x, ef, W1, b1, idxn, degs, out, E);
}